// round 1
// baseline (speedup 1.0000x reference)
#include <cuda_runtime.h>

#define B_      16
#define NP      196
#define NT      197
#define D_      768
#define M_      3072
#define HEADS_  12
#define Y_      64
#define NSTEPS_ 12
#define ALPHA_  0.1f
#define BETA_   0.125f
#define EPS_    1e-5f
#define NMASK_  100

// ---------------- scratch (device globals; no runtime allocation) ----------------
__device__ float d_patches[B_*NP*D_];
__device__ float d_tok[B_*NP*D_];
__device__ float d_x[B_*NT*D_];
__device__ float d_g[B_*NT*D_];
__device__ float d_qb[B_*NT*D_];
__device__ float d_kb[B_*NT*D_];
__device__ float d_P[B_*HEADS_*NT*NT];
__device__ float d_oq[B_*NT*D_];
__device__ float d_ok[B_*NT*D_];
__device__ float d_Z[B_*NT*M_];
__device__ float d_Wq2[D_*D_];
__device__ float d_Wk2[D_*D_];
__device__ float d_dec[B_*NP*D_];

// ---------------- generic strided batched SGEMM ----------------
// C[m,n] (+)= op over k of A(m,k)*B(k,n)
// A(m,k) at A[m*sAm + k*sAk] (+batch offset), B(k,n) at B[k*sBk + n*sBn]
// batch index z = zo*innerB + zi ; offsets oXo*zo + oXi*zi
#define EPI_STORE 0
#define EPI_BIAS  1
#define EPI_RELU  2
#define EPI_AXPY  3

template<int EPI>
__global__ void __launch_bounds__(256, 2) gemm_kernel(
    const float* __restrict__ A, const float* __restrict__ B,
    float* __restrict__ C, const float* __restrict__ bias,
    int M, int N, int K, int ldc,
    int sAm, int sAk, int sBk, int sBn,
    long long oAo, long long oAi,
    long long oBo, long long oBi,
    long long oCo, long long oCi,
    int innerB, float alpha)
{
    int z  = blockIdx.z;
    int zo = z / innerB, zi = z - zo*innerB;
    A += zo*oAo + zi*oAi;
    B += zo*oBo + zi*oBi;
    C += zo*oCo + zi*oCi;

    __shared__ float As[8][128];
    __shared__ float Bs[8][128];

    int row0 = blockIdx.y * 128;
    int col0 = blockIdx.x * 128;
    int tid  = threadIdx.x;
    int lrow = tid >> 1;
    int lk4  = (tid & 1) * 4;
    int tx   = (tid & 15) * 8;
    int ty   = (tid >> 4) * 8;

    float acc[8][8];
#pragma unroll
    for (int i = 0; i < 8; i++)
#pragma unroll
        for (int j = 0; j < 8; j++) acc[i][j] = 0.f;

    for (int k0 = 0; k0 < K; k0 += 8) {
        int m = row0 + lrow;
#pragma unroll
        for (int i = 0; i < 4; i++) {
            int kk = k0 + lk4 + i;
            float v = 0.f;
            if (m < M && kk < K)
                v = A[(long long)m * sAm + (long long)kk * sAk];
            As[lk4 + i][lrow] = v;
        }
        int n = col0 + lrow;
#pragma unroll
        for (int i = 0; i < 4; i++) {
            int kk = k0 + lk4 + i;
            float v = 0.f;
            if (n < N && kk < K)
                v = B[(long long)kk * sBk + (long long)n * sBn];
            Bs[lk4 + i][lrow] = v;
        }
        __syncthreads();
#pragma unroll
        for (int kk = 0; kk < 8; kk++) {
            float a[8], b[8];
#pragma unroll
            for (int i = 0; i < 8; i++) a[i] = As[kk][ty + i];
#pragma unroll
            for (int j = 0; j < 8; j++) b[j] = Bs[kk][tx + j];
#pragma unroll
            for (int i = 0; i < 8; i++)
#pragma unroll
                for (int j = 0; j < 8; j++)
                    acc[i][j] += a[i] * b[j];
        }
        __syncthreads();
    }

#pragma unroll
    for (int i = 0; i < 8; i++) {
        int m = row0 + ty + i;
        if (m < M) {
            float* crow = C + (long long)m * ldc;
#pragma unroll
            for (int j = 0; j < 8; j++) {
                int n = col0 + tx + j;
                if (n < N) {
                    float v = acc[i][j];
                    if (EPI == EPI_BIAS) v += bias[n];
                    if (EPI == EPI_RELU) v = fmaxf(v, 0.f);
                    if (EPI == EPI_AXPY) v = crow[n] + alpha * v;
                    crow[n] = v;
                }
            }
        }
    }
}

// ---------------- layernorm ----------------
__device__ __forceinline__ float block_sum256(float v, float* red) {
    int lane = threadIdx.x & 31, w = threadIdx.x >> 5;
#pragma unroll
    for (int o = 16; o > 0; o >>= 1) v += __shfl_xor_sync(0xffffffffu, v, o);
    if (lane == 0) red[w] = v;
    __syncthreads();
    float s = 0.f;
#pragma unroll
    for (int i = 0; i < 8; i++) s += red[i];
    __syncthreads();
    return s;
}

__global__ void lnorm_kernel(const float* __restrict__ x, float* __restrict__ g,
                             const float* __restrict__ gamma_p,
                             const float* __restrict__ delta, int skipcls)
{
    __shared__ float red[8];
    int r = blockIdx.x;
    const float* xr;
    float* gr;
    if (skipcls) {
        int b = r / NP, i = r - b * NP;
        xr = x + (long long)(b * NT + 1 + i) * D_;
        gr = g + (long long)r * D_;
    } else {
        xr = x + (long long)r * D_;
        gr = g + (long long)r * D_;
    }
    int t = threadIdx.x; // 256
    float v0 = xr[t], v1 = xr[t + 256], v2 = xr[t + 512];
    float mean = block_sum256(v0 + v1 + v2, red) * (1.f / 768.f);
    float c0 = v0 - mean, c1 = v1 - mean, c2 = v2 - mean;
    float var = block_sum256(c0*c0 + c1*c1 + c2*c2, red) * (1.f / 768.f);
    float rinv = rsqrtf(var + EPS_);
    float gm = gamma_p[0];
    gr[t]       = gm * c0 * rinv + delta[t];
    gr[t + 256] = gm * c1 * rinv + delta[t + 256];
    gr[t + 512] = gm * c2 * rinv + delta[t + 512];
}

// ---------------- softmax over attention rows (applies BETA) ----------------
__global__ void softmax_kernel(float* __restrict__ P)
{
    __shared__ float red[4];
    long long row = blockIdx.x;
    float* p = P + row * NT;
    int t = threadIdx.x;          // 128
    int lane = t & 31, w = t >> 5;
    float a0 = (t < NT)       ? p[t]       : -1e30f;
    float a1 = (t + 128 < NT) ? p[t + 128] : -1e30f;
    float mx = fmaxf(a0, a1);
#pragma unroll
    for (int o = 16; o > 0; o >>= 1) mx = fmaxf(mx, __shfl_xor_sync(0xffffffffu, mx, o));
    if (lane == 0) red[w] = mx;
    __syncthreads();
    mx = fmaxf(fmaxf(red[0], red[1]), fmaxf(red[2], red[3]));
    __syncthreads();
    float e0 = (t < NT)       ? expf(BETA_ * (a0 - mx)) : 0.f;
    float e1 = (t + 128 < NT) ? expf(BETA_ * (a1 - mx)) : 0.f;
    float s = e0 + e1;
#pragma unroll
    for (int o = 16; o > 0; o >>= 1) s += __shfl_xor_sync(0xffffffffu, s, o);
    if (lane == 0) red[w] = s;
    __syncthreads();
    s = red[0] + red[1] + red[2] + red[3];
    float inv = 1.f / s;
    if (t < NT)       p[t]       = e0 * inv;
    if (t + 128 < NT) p[t + 128] = e1 * inv;
}

// ---------------- small utility kernels ----------------
__global__ void transpose_w_kernel(const float* __restrict__ W, float* __restrict__ W2)
{
    int idx = blockIdx.x * 256 + threadIdx.x;
    if (idx >= HEADS_ * D_ * Y_) return;
    int h = idx / (D_ * Y_);
    int rem = idx - h * (D_ * Y_);
    int d = rem / Y_;
    int y = rem - d * Y_;
    W2[d * D_ + h * Y_ + y] = W[idx];
}

__global__ void patchify_kernel(const float* __restrict__ img, float* __restrict__ out)
{
    int idx = blockIdx.x * 256 + threadIdx.x;
    if (idx >= B_ * NP * D_) return;
    int e = idx % D_;
    int rest = idx / D_;
    int p = rest % NP;
    int b = rest / NP;
    int c = e >> 8;
    int r = (e >> 4) & 15;
    int col = e & 15;
    int kh = p / 14, kw = p - kh * 14;
    out[idx] = img[((long long)(b * 3 + c) * 224 + kh * 16 + r) * 224 + kw * 16 + col];
}

__global__ void unpatchify_kernel(const float* __restrict__ dec, float* __restrict__ out)
{
    int idx = blockIdx.x * 256 + threadIdx.x;
    if (idx >= B_ * 3 * 224 * 224) return;
    int w = idx % 224;
    int rest = idx / 224;
    int h = rest % 224;
    rest /= 224;
    int c = rest % 3;
    int b = rest / 3;
    int kh = h >> 4, r = h & 15, kw = w >> 4, col = w & 15;
    out[idx] = dec[(long long)(b * NP + kh * 14 + kw) * D_ + c * 256 + r * 16 + col];
}

// replicate jnp.nonzero(mask==1, size=100, fill_value=0) + at[idx].set semantics
__global__ void build_x_kernel(const float* __restrict__ tok, const int* __restrict__ mask,
                               const float* __restrict__ cls, const float* __restrict__ mtok,
                               const float* __restrict__ pos, float* __restrict__ x)
{
    __shared__ int sm[NP];
    __shared__ unsigned char flag[NP];
    __shared__ int count_s;
    int b = blockIdx.x;
    int t = threadIdx.x; // 256
    if (t < NP) sm[t] = mask[b * NP + t];
    __syncthreads();
    if (t < NP) {
        int pref = 0;
        for (int j = 0; j < t; j++) pref += (sm[j] == 1);
        flag[t] = (sm[t] == 1 && pref < NMASK_) ? 1 : 0;
        if (t == NP - 1) count_s = pref + (sm[t] == 1);
    }
    __syncthreads();
    if (t == 0 && count_s < NMASK_) flag[0] = 1; // fill_value=0 padding hits token 0
    __syncthreads();
    for (int tk = 0; tk < NT; tk++) {
        const float* src;
        if (tk == 0) src = cls;
        else if (flag[tk - 1]) src = mtok;
        else src = tok + (long long)(b * NP + tk - 1) * D_;
        float* dst = x + (long long)(b * NT + tk) * D_;
        const float* pr = pos + (long long)tk * D_;
        for (int d = t; d < D_; d += 256) dst[d] = src[d] + pr[d];
    }
}

// ---------------- host-side gemm wrapper ----------------
struct GP {
    const float *A, *B;
    float* C;
    const float* bias;
    int M, N, K, ldc;
    int sAm, sAk, sBk, sBn;
    long long oAo, oAi, oBo, oBi, oCo, oCi;
    int innerB, batch;
    float alpha;
};

template<int EPI>
static void launch_gemm(const GP& p) {
    dim3 g((p.N + 127) / 128, (p.M + 127) / 128, p.batch);
    gemm_kernel<EPI><<<g, 256>>>(p.A, p.B, p.C, p.bias,
        p.M, p.N, p.K, p.ldc, p.sAm, p.sAk, p.sBk, p.sBn,
        p.oAo, p.oAi, p.oBo, p.oBi, p.oCo, p.oCi, p.innerB, p.alpha);
}

extern "C" void kernel_launch(void* const* d_in, const int* in_sizes, int n_in,
                              void* d_out, int out_size)
{
    const float* img   = (const float*)d_in[0];
    const int*   mask  = (const int*)  d_in[1];
    const float* enc_W = (const float*)d_in[2];
    const float* enc_b = (const float*)d_in[3];
    const float* dec_W = (const float*)d_in[4];
    const float* dec_b = (const float*)d_in[5];
    const float* cls   = (const float*)d_in[6];
    const float* mtok  = (const float*)d_in[7];
    const float* pos   = (const float*)d_in[8];
    const float* Wq    = (const float*)d_in[9];
    const float* Wk    = (const float*)d_in[10];
    const float* Xi    = (const float*)d_in[11];
    const float* gamma = (const float*)d_in[12];
    const float* delta = (const float*)d_in[13];
    float* out = (float*)d_out;

    float *ppat, *ptok, *px, *pg, *pq, *pk, *pP, *poq, *pok, *pZ, *pWq2, *pWk2, *pdec;
    cudaGetSymbolAddress((void**)&ppat, d_patches);
    cudaGetSymbolAddress((void**)&ptok, d_tok);
    cudaGetSymbolAddress((void**)&px,   d_x);
    cudaGetSymbolAddress((void**)&pg,   d_g);
    cudaGetSymbolAddress((void**)&pq,   d_qb);
    cudaGetSymbolAddress((void**)&pk,   d_kb);
    cudaGetSymbolAddress((void**)&pP,   d_P);
    cudaGetSymbolAddress((void**)&poq,  d_oq);
    cudaGetSymbolAddress((void**)&pok,  d_ok);
    cudaGetSymbolAddress((void**)&pZ,   d_Z);
    cudaGetSymbolAddress((void**)&pWq2, d_Wq2);
    cudaGetSymbolAddress((void**)&pWk2, d_Wk2);
    cudaGetSymbolAddress((void**)&pdec, d_dec);

    const int ROWS  = B_ * NT;   // 3152
    const int ROWSE = B_ * NP;   // 3136
    const long long PB = (long long)NT * NT;        // per-head P slice
    const long long GB = (long long)NT * D_;        // per-batch token-row block

    // Wq/Wk -> (D, H*Y)
    int wn = HEADS_ * D_ * Y_;
    transpose_w_kernel<<<(wn + 255) / 256, 256>>>(Wq, pWq2);
    transpose_w_kernel<<<(wn + 255) / 256, 256>>>(Wk, pWk2);

    // encode
    patchify_kernel<<<(B_ * NP * D_ + 255) / 256, 256>>>(img, ppat);
    {   // tok = patches @ enc_W + enc_b
        GP p = { ppat, enc_W, ptok, enc_b, ROWSE, D_, D_, D_,
                 D_, 1, D_, 1, 0,0,0,0,0,0, 1, 1, 0.f };
        launch_gemm<EPI_BIAS>(p);
    }
    build_x_kernel<<<B_, 256>>>(ptok, mask, cls, mtok, pos, px);

    for (int s = 0; s < NSTEPS_; s++) {
        lnorm_kernel<<<ROWS, 256>>>(px, pg, gamma, delta, 0);
        {   // q = g @ Wq2
            GP p = { pg, pWq2, pq, 0, ROWS, D_, D_, D_,
                     D_, 1, D_, 1, 0,0,0,0,0,0, 1, 1, 0.f };
            launch_gemm<EPI_STORE>(p);
        }
        {   // k = g @ Wk2
            GP p = { pg, pWk2, pk, 0, ROWS, D_, D_, D_,
                     D_, 1, D_, 1, 0,0,0,0,0,0, 1, 1, 0.f };
            launch_gemm<EPI_STORE>(p);
        }
        {   // S[b,h,n,m] = q_h[n,:] . k_h[m,:]   batch z=(b,h)
            GP p = { pq, pk, pP, 0, NT, NT, Y_, NT,
                     D_, 1, 1, D_,
                     GB, Y_,  GB, Y_,  HEADS_ * PB, PB,
                     HEADS_, B_ * HEADS_, 0.f };
            launch_gemm<EPI_STORE>(p);
        }
        softmax_kernel<<<B_ * HEADS_ * NT, 128>>>(pP);
        {   // outq = P @ k_h
            GP p = { pP, pk, poq, 0, NT, Y_, NT, D_,
                     NT, 1, D_, 1,
                     HEADS_ * PB, PB,  GB, Y_,  GB, Y_,
                     HEADS_, B_ * HEADS_, 0.f };
            launch_gemm<EPI_STORE>(p);
        }
        {   // outk = P^T @ q_h
            GP p = { pP, pq, pok, 0, NT, Y_, NT, D_,
                     1, NT, D_, 1,
                     HEADS_ * PB, PB,  GB, Y_,  GB, Y_,
                     HEADS_, B_ * HEADS_, 0.f };
            launch_gemm<EPI_STORE>(p);
        }
        {   // x += alpha * outq @ Wq2^T
            GP p = { poq, pWq2, px, 0, ROWS, D_, D_, D_,
                     D_, 1, 1, D_, 0,0,0,0,0,0, 1, 1, ALPHA_ };
            launch_gemm<EPI_AXPY>(p);
        }
        {   // x += alpha * outk @ Wk2^T
            GP p = { pok, pWk2, px, 0, ROWS, D_, D_, D_,
                     D_, 1, 1, D_, 0,0,0,0,0,0, 1, 1, ALPHA_ };
            launch_gemm<EPI_AXPY>(p);
        }
        {   // Z = relu(g @ Xi)
            GP p = { pg, Xi, pZ, 0, ROWS, M_, D_, M_,
                     D_, 1, M_, 1, 0,0,0,0,0,0, 1, 1, 0.f };
            launch_gemm<EPI_RELU>(p);
        }
        {   // x += alpha * Z @ Xi^T
            GP p = { pZ, Xi, px, 0, ROWS, D_, M_, D_,
                     M_, 1, 1, M_, 0,0,0,0,0,0, 1, 1, ALPHA_ };
            launch_gemm<EPI_AXPY>(p);
        }
    }

    // decode
    lnorm_kernel<<<ROWSE, 256>>>(px, pg, gamma, delta, 1);
    {   // dec = g @ dec_W + dec_b
        GP p = { pg, dec_W, pdec, dec_b, ROWSE, D_, D_, D_,
                 D_, 1, D_, 1, 0,0,0,0,0,0, 1, 1, 0.f };
        launch_gemm<EPI_BIAS>(p);
    }
    unpatchify_kernel<<<(B_ * 3 * 224 * 224 + 255) / 256, 256>>>(pdec, out);
}

// round 3
// speedup vs baseline: 2.1400x; 2.1400x over previous
#include <cuda_runtime.h>
#include <cstdint>

#define B_      16
#define NP      196
#define NT      197
#define D_      768
#define M_      3072
#define HEADS_  12
#define Y_      64
#define NSTEPS_ 12
#define ALPHA_  0.1f
#define BETA_   0.125f
#define EPS_    1e-5f
#define NMASK_  100
#define RP      3200          // padded row count (25 * 128)
#define QKW     1536          // fused q|k width

// ---------------- scratch (device globals; zero-initialized) ----------------
__device__ float d_patches[B_*NP*D_];
__device__ float d_tok[B_*NP*D_];
__device__ float d_x[RP*D_];
__device__ float d_g[RP*D_];
__device__ float d_qk[RP*QKW];
__device__ float d_oqk[RP*QKW];
__device__ float d_P[B_*HEADS_*NT*NT];
__device__ float d_Z[RP*M_];
__device__ float d_W2[D_*QKW];    // [d][hy|768+hy]  B for back-projection
__device__ float d_WT[QKW*D_];    // [hy][d]         B for projection
__device__ float d_XiT[M_*D_];    // [m][d]          B for hopfield fwd
__device__ float d_dec[B_*NP*D_];

#define EPI_STORE 0
#define EPI_BIAS  1
#define EPI_RELU  2
#define EPI_AXPY  3

// ================= tf32 mma.sync GEMM =================
// C[RP x N] (+)= A[RP x K] * B^T,  B stored [N x K] row-major (k-major rows).
// Block 128x128, BK=16, 128 threads = 4 warps in 2x2 grid of 64x64 warp tiles.
// smem tiles padded to stride 20 floats (conflict-free fragment loads).

__device__ __forceinline__ uint32_t smem_u32(const void* p) {
    uint32_t a;
    asm("{ .reg .u64 t; cvta.to.shared.u64 t, %1; cvt.u32.u64 %0, t; }" : "=r"(a) : "l"(p));
    return a;
}

__device__ __forceinline__ uint32_t f2tf32(float v) {
    uint32_t u;
    asm("cvt.rna.tf32.f32 %0, %1;" : "=r"(u) : "f"(v));
    return u;
}

__device__ __forceinline__ void ldtile_async(float* s, const float* gp, int ld, int tid) {
    // 128 rows x 16 floats; thread t loads row t (4 x 16B)
    const float* grow = gp + (long long)tid * ld;
    uint32_t srow = smem_u32(s + tid * 20);
#pragma unroll
    for (int seg = 0; seg < 4; seg++) {
        asm volatile("cp.async.cg.shared.global [%0], [%1], 16;"
                     :: "r"(srow + seg * 16), "l"(grow + seg * 4));
    }
}

template<int EPI>
__global__ __launch_bounds__(128, 2) void mma_gemm_kernel(
    const float* __restrict__ A, const float* __restrict__ Bm,
    float* __restrict__ C, int K, int lda, int ldb, int ldc, float alpha)
{
    extern __shared__ float sm[];
    float* sA[2] = { sm,             sm + 2 * 2560 };
    float* sB[2] = { sm + 2560,      sm + 3 * 2560 };

    const int tid = threadIdx.x;
    const int lane = tid & 31, wid = tid >> 5;
    const int grp = lane >> 2, tig = lane & 3;
    const int wm = (wid >> 1) * 64, wn = (wid & 1) * 64;
    const long long m0 = (long long)blockIdx.y * 128;
    const long long n0 = (long long)blockIdx.x * 128;
    A += m0 * lda;
    Bm += n0 * ldb;

    float acc[4][8][4];
#pragma unroll
    for (int i = 0; i < 4; i++)
#pragma unroll
        for (int j = 0; j < 8; j++)
#pragma unroll
            for (int c = 0; c < 4; c++) acc[i][j][c] = 0.f;

    const int nk = K >> 4;
    ldtile_async(sA[0], A, lda, tid);
    ldtile_async(sB[0], Bm, ldb, tid);
    asm volatile("cp.async.commit_group;" ::: "memory");

    for (int kt = 0; kt < nk; kt++) {
        if (kt + 1 < nk) {
            ldtile_async(sA[(kt + 1) & 1], A + (kt + 1) * 16, lda, tid);
            ldtile_async(sB[(kt + 1) & 1], Bm + (kt + 1) * 16, ldb, tid);
            asm volatile("cp.async.commit_group;" ::: "memory");
            asm volatile("cp.async.wait_group 1;" ::: "memory");
        } else {
            asm volatile("cp.async.wait_group 0;" ::: "memory");
        }
        __syncthreads();

        const float* cA = sA[kt & 1];
        const float* cB = sB[kt & 1];
#pragma unroll
        for (int kk = 0; kk < 16; kk += 8) {
            uint32_t af[4][4], bf[8][2];
#pragma unroll
            for (int mt = 0; mt < 4; mt++) {
                const float* p = cA + (wm + mt * 16 + grp) * 20 + kk + tig;
                af[mt][0] = f2tf32(p[0]);
                af[mt][2] = f2tf32(p[4]);
                af[mt][1] = f2tf32(p[8 * 20]);
                af[mt][3] = f2tf32(p[8 * 20 + 4]);
            }
#pragma unroll
            for (int nt = 0; nt < 8; nt++) {
                const float* p = cB + (wn + nt * 8 + grp) * 20 + kk + tig;
                bf[nt][0] = f2tf32(p[0]);
                bf[nt][1] = f2tf32(p[4]);
            }
#pragma unroll
            for (int mt = 0; mt < 4; mt++)
#pragma unroll
                for (int nt = 0; nt < 8; nt++) {
                    asm("mma.sync.aligned.m16n8k8.row.col.f32.tf32.tf32.f32 "
                        "{%0,%1,%2,%3}, {%4,%5,%6,%7}, {%8,%9}, {%0,%1,%2,%3};"
                        : "+f"(acc[mt][nt][0]), "+f"(acc[mt][nt][1]),
                          "+f"(acc[mt][nt][2]), "+f"(acc[mt][nt][3])
                        : "r"(af[mt][0]), "r"(af[mt][1]), "r"(af[mt][2]), "r"(af[mt][3]),
                          "r"(bf[nt][0]), "r"(bf[nt][1]));
                }
        }
        __syncthreads();
    }

    // epilogue
#pragma unroll
    for (int mt = 0; mt < 4; mt++) {
        long long r0 = m0 + wm + mt * 16 + grp;
        float* c0 = C + r0 * ldc + n0 + wn;
        float* c1 = c0 + 8LL * ldc;
#pragma unroll
        for (int nt = 0; nt < 8; nt++) {
            int col = nt * 8 + 2 * tig;
            float2 v0 = make_float2(acc[mt][nt][0], acc[mt][nt][1]);
            float2 v1 = make_float2(acc[mt][nt][2], acc[mt][nt][3]);
            if (EPI == EPI_RELU) {
                v0.x = fmaxf(v0.x, 0.f); v0.y = fmaxf(v0.y, 0.f);
                v1.x = fmaxf(v1.x, 0.f); v1.y = fmaxf(v1.y, 0.f);
            }
            if (EPI == EPI_AXPY) {
                float2 o0 = *(float2*)(c0 + col);
                float2 o1 = *(float2*)(c1 + col);
                v0.x = o0.x + alpha * v0.x; v0.y = o0.y + alpha * v0.y;
                v1.x = o1.x + alpha * v1.x; v1.y = o1.y + alpha * v1.y;
            }
            *(float2*)(c0 + col) = v0;
            *(float2*)(c1 + col) = v1;
        }
    }
}

// ================= fp32 strided batched SGEMM (attention / encode / decode) =================
template<int EPI>
__global__ void __launch_bounds__(256, 2) gemm_kernel(
    const float* __restrict__ A, const float* __restrict__ B,
    float* __restrict__ C, const float* __restrict__ bias,
    int M, int N, int K, int ldc,
    int sAm, int sAk, int sBk, int sBn,
    long long oAo, long long oAi,
    long long oBo, long long oBi,
    long long oCo, long long oCi,
    int innerB, float alpha)
{
    int z  = blockIdx.z;
    int zo = z / innerB, zi = z - zo * innerB;
    A += zo * oAo + zi * oAi;
    B += zo * oBo + zi * oBi;
    C += zo * oCo + zi * oCi;

    __shared__ float As[8][128];
    __shared__ float Bs[8][128];

    int row0 = blockIdx.y * 128;
    int col0 = blockIdx.x * 128;
    int tid  = threadIdx.x;
    int lrow = tid >> 1;
    int lk4  = (tid & 1) * 4;
    int tx   = (tid & 15) * 8;
    int ty   = (tid >> 4) * 8;

    float acc[8][8];
#pragma unroll
    for (int i = 0; i < 8; i++)
#pragma unroll
        for (int j = 0; j < 8; j++) acc[i][j] = 0.f;

    for (int k0 = 0; k0 < K; k0 += 8) {
        int m = row0 + lrow;
#pragma unroll
        for (int i = 0; i < 4; i++) {
            int kk = k0 + lk4 + i;
            float v = 0.f;
            if (m < M && kk < K)
                v = A[(long long)m * sAm + (long long)kk * sAk];
            As[lk4 + i][lrow] = v;
        }
        int n = col0 + lrow;
#pragma unroll
        for (int i = 0; i < 4; i++) {
            int kk = k0 + lk4 + i;
            float v = 0.f;
            if (n < N && kk < K)
                v = B[(long long)kk * sBk + (long long)n * sBn];
            Bs[lk4 + i][lrow] = v;
        }
        __syncthreads();
#pragma unroll
        for (int kk = 0; kk < 8; kk++) {
            float a[8], b[8];
#pragma unroll
            for (int i = 0; i < 8; i++) a[i] = As[kk][ty + i];
#pragma unroll
            for (int j = 0; j < 8; j++) b[j] = Bs[kk][tx + j];
#pragma unroll
            for (int i = 0; i < 8; i++)
#pragma unroll
                for (int j = 0; j < 8; j++)
                    acc[i][j] += a[i] * b[j];
        }
        __syncthreads();
    }

#pragma unroll
    for (int i = 0; i < 8; i++) {
        int m = row0 + ty + i;
        if (m < M) {
            float* crow = C + (long long)m * ldc;
#pragma unroll
            for (int j = 0; j < 8; j++) {
                int n = col0 + tx + j;
                if (n < N) {
                    float v = acc[i][j];
                    if (EPI == EPI_BIAS) v += bias[n];
                    if (EPI == EPI_RELU) v = fmaxf(v, 0.f);
                    if (EPI == EPI_AXPY) v = crow[n] + alpha * v;
                    crow[n] = v;
                }
            }
        }
    }
}

// ================= layernorm =================
__device__ __forceinline__ float block_sum256(float v, float* red) {
    int lane = threadIdx.x & 31, w = threadIdx.x >> 5;
#pragma unroll
    for (int o = 16; o > 0; o >>= 1) v += __shfl_xor_sync(0xffffffffu, v, o);
    if (lane == 0) red[w] = v;
    __syncthreads();
    float s = 0.f;
#pragma unroll
    for (int i = 0; i < 8; i++) s += red[i];
    __syncthreads();
    return s;
}

__global__ void lnorm_kernel(const float* __restrict__ x, float* __restrict__ g,
                             const float* __restrict__ gamma_p,
                             const float* __restrict__ delta, int skipcls)
{
    __shared__ float red[8];
    int r = blockIdx.x;
    const float* xr;
    float* gr;
    if (skipcls) {
        int b = r / NP, i = r - b * NP;
        xr = x + (long long)(b * NT + 1 + i) * D_;
        gr = g + (long long)r * D_;
    } else {
        xr = x + (long long)r * D_;
        gr = g + (long long)r * D_;
    }
    int t = threadIdx.x; // 256
    float v0 = xr[t], v1 = xr[t + 256], v2 = xr[t + 512];
    float mean = block_sum256(v0 + v1 + v2, red) * (1.f / 768.f);
    float c0 = v0 - mean, c1 = v1 - mean, c2 = v2 - mean;
    float var = block_sum256(c0*c0 + c1*c1 + c2*c2, red) * (1.f / 768.f);
    float rinv = rsqrtf(var + EPS_);
    float gm = gamma_p[0];
    gr[t]       = gm * c0 * rinv + delta[t];
    gr[t + 256] = gm * c1 * rinv + delta[t + 256];
    gr[t + 512] = gm * c2 * rinv + delta[t + 512];
}

// ================= softmax =================
__global__ void softmax_kernel(float* __restrict__ P)
{
    __shared__ float red[4];
    long long row = blockIdx.x;
    float* p = P + row * NT;
    int t = threadIdx.x;          // 128
    int lane = t & 31, w = t >> 5;
    float a0 = (t < NT)       ? p[t]       : -1e30f;
    float a1 = (t + 128 < NT) ? p[t + 128] : -1e30f;
    float mx = fmaxf(a0, a1);
#pragma unroll
    for (int o = 16; o > 0; o >>= 1) mx = fmaxf(mx, __shfl_xor_sync(0xffffffffu, mx, o));
    if (lane == 0) red[w] = mx;
    __syncthreads();
    mx = fmaxf(fmaxf(red[0], red[1]), fmaxf(red[2], red[3]));
    __syncthreads();
    float e0 = (t < NT)       ? expf(BETA_ * (a0 - mx)) : 0.f;
    float e1 = (t + 128 < NT) ? expf(BETA_ * (a1 - mx)) : 0.f;
    float s = e0 + e1;
#pragma unroll
    for (int o = 16; o > 0; o >>= 1) s += __shfl_xor_sync(0xffffffffu, s, o);
    if (lane == 0) red[w] = s;
    __syncthreads();
    s = red[0] + red[1] + red[2] + red[3];
    float inv = 1.f / s;
    if (t < NT)       p[t]       = e0 * inv;
    if (t + 128 < NT) p[t + 128] = e1 * inv;
}

// ================= small utility kernels =================
__global__ void build_wqk_kernel(const float* __restrict__ Wq, const float* __restrict__ Wk,
                                 float* __restrict__ W2, float* __restrict__ WT)
{
    int idx = blockIdx.x * 256 + threadIdx.x;
    if (idx >= 2 * D_ * D_) return;
    int which = idx >= D_ * D_;
    int r = idx - which * D_ * D_;
    int h = r / (D_ * Y_);
    int rem = r - h * (D_ * Y_);
    int d = rem / Y_;
    int y = rem - d * Y_;
    float v = which ? Wk[r] : Wq[r];
    int hy = h * Y_ + y + which * D_;
    W2[d * QKW + hy] = v;
    WT[(long long)hy * D_ + d] = v;
}

__global__ void build_xit_kernel(const float* __restrict__ Xi, float* __restrict__ XiT)
{
    int idx = blockIdx.x * 256 + threadIdx.x;
    if (idx >= D_ * M_) return;
    int d = idx / M_, m = idx - d * M_;
    XiT[(long long)m * D_ + d] = Xi[idx];
}

__global__ void patchify_kernel(const float* __restrict__ img, float* __restrict__ out)
{
    int idx = blockIdx.x * 256 + threadIdx.x;
    if (idx >= B_ * NP * D_) return;
    int e = idx % D_;
    int rest = idx / D_;
    int p = rest % NP;
    int b = rest / NP;
    int c = e >> 8;
    int r = (e >> 4) & 15;
    int col = e & 15;
    int kh = p / 14, kw = p - kh * 14;
    out[idx] = img[((long long)(b * 3 + c) * 224 + kh * 16 + r) * 224 + kw * 16 + col];
}

__global__ void unpatchify_kernel(const float* __restrict__ dec, float* __restrict__ out)
{
    int idx = blockIdx.x * 256 + threadIdx.x;
    if (idx >= B_ * 3 * 224 * 224) return;
    int w = idx % 224;
    int rest = idx / 224;
    int h = rest % 224;
    rest /= 224;
    int c = rest % 3;
    int b = rest / 3;
    int kh = h >> 4, r = h & 15, kw = w >> 4, col = w & 15;
    out[idx] = dec[(long long)(b * NP + kh * 14 + kw) * D_ + c * 256 + r * 16 + col];
}

__global__ void build_x_kernel(const float* __restrict__ tok, const int* __restrict__ mask,
                               const float* __restrict__ cls, const float* __restrict__ mtok,
                               const float* __restrict__ pos, float* __restrict__ x)
{
    __shared__ int sm[NP];
    __shared__ unsigned char flag[NP];
    __shared__ int count_s;
    int b = blockIdx.x;
    int t = threadIdx.x; // 256
    if (t < NP) sm[t] = mask[b * NP + t];
    __syncthreads();
    if (t < NP) {
        int pref = 0;
        for (int j = 0; j < t; j++) pref += (sm[j] == 1);
        flag[t] = (sm[t] == 1 && pref < NMASK_) ? 1 : 0;
        if (t == NP - 1) count_s = pref + (sm[t] == 1);
    }
    __syncthreads();
    if (t == 0 && count_s < NMASK_) flag[0] = 1; // fill_value=0 padding hits token 0
    __syncthreads();
    for (int tk = 0; tk < NT; tk++) {
        const float* src;
        if (tk == 0) src = cls;
        else if (flag[tk - 1]) src = mtok;
        else src = tok + (long long)(b * NP + tk - 1) * D_;
        float* dst = x + (long long)(b * NT + tk) * D_;
        const float* pr = pos + (long long)tk * D_;
        for (int d = t; d < D_; d += 256) dst[d] = src[d] + pr[d];
    }
}

// ================= host wrappers =================
struct GP {
    const float *A, *B;
    float* C;
    const float* bias;
    int M, N, K, ldc;
    int sAm, sAk, sBk, sBn;
    long long oAo, oAi, oBo, oBi, oCo, oCi;
    int innerB, batch;
    float alpha;
};

template<int EPI>
static void launch_gemm(const GP& p) {
    dim3 g((p.N + 127) / 128, (p.M + 127) / 128, p.batch);
    gemm_kernel<EPI><<<g, 256>>>(p.A, p.B, p.C, p.bias,
        p.M, p.N, p.K, p.ldc, p.sAm, p.sAk, p.sBk, p.sBn,
        p.oAo, p.oAi, p.oBo, p.oBi, p.oCo, p.oCi, p.innerB, p.alpha);
}

template<int EPI>
static void launch_mgemm(const float* A, const float* B, float* C,
                         int N, int K, int lda, int ldb, int ldc, float alpha) {
    dim3 g(N / 128, RP / 128);
    size_t smem = 4 * 2560 * sizeof(float);   // 40 KB (2 stages x (A+B))
    mma_gemm_kernel<EPI><<<g, 128, smem>>>(A, B, C, K, lda, ldb, ldc, alpha);
}

extern "C" void kernel_launch(void* const* d_in, const int* in_sizes, int n_in,
                              void* d_out, int out_size)
{
    const float* img   = (const float*)d_in[0];
    const int*   mask  = (const int*)  d_in[1];
    const float* enc_W = (const float*)d_in[2];
    const float* enc_b = (const float*)d_in[3];
    const float* dec_W = (const float*)d_in[4];
    const float* dec_b = (const float*)d_in[5];
    const float* cls   = (const float*)d_in[6];
    const float* mtok  = (const float*)d_in[7];
    const float* pos   = (const float*)d_in[8];
    const float* Wq    = (const float*)d_in[9];
    const float* Wk    = (const float*)d_in[10];
    const float* Xi    = (const float*)d_in[11];
    const float* gamma = (const float*)d_in[12];
    const float* delta = (const float*)d_in[13];
    float* out = (float*)d_out;

    float *ppat, *ptok, *px, *pg, *pqk, *poqk, *pP, *pZ, *pW2, *pWT, *pXiT, *pdec;
    cudaGetSymbolAddress((void**)&ppat, d_patches);
    cudaGetSymbolAddress((void**)&ptok, d_tok);
    cudaGetSymbolAddress((void**)&px,   d_x);
    cudaGetSymbolAddress((void**)&pg,   d_g);
    cudaGetSymbolAddress((void**)&pqk,  d_qk);
    cudaGetSymbolAddress((void**)&poqk, d_oqk);
    cudaGetSymbolAddress((void**)&pP,   d_P);
    cudaGetSymbolAddress((void**)&pZ,   d_Z);
    cudaGetSymbolAddress((void**)&pW2,  d_W2);
    cudaGetSymbolAddress((void**)&pWT,  d_WT);
    cudaGetSymbolAddress((void**)&pXiT, d_XiT);
    cudaGetSymbolAddress((void**)&pdec, d_dec);

    const int ROWS  = B_ * NT;   // 3152
    const int ROWSE = B_ * NP;   // 3136
    const long long PB2 = (long long)NT * NT;
    const long long GB2 = (long long)NT * QKW;

    // weight reshapes
    build_wqk_kernel<<<(2 * D_ * D_ + 255) / 256, 256>>>(Wq, Wk, pW2, pWT);
    build_xit_kernel<<<(D_ * M_ + 255) / 256, 256>>>(Xi, pXiT);

    // encode
    patchify_kernel<<<(B_ * NP * D_ + 255) / 256, 256>>>(img, ppat);
    {   GP p = { ppat, enc_W, ptok, enc_b, ROWSE, D_, D_, D_,
                 D_, 1, D_, 1, 0,0,0,0,0,0, 1, 1, 0.f };
        launch_gemm<EPI_BIAS>(p);
    }
    build_x_kernel<<<B_, 256>>>(ptok, mask, cls, mtok, pos, px);

    for (int s = 0; s < NSTEPS_; s++) {
        lnorm_kernel<<<ROWS, 256>>>(px, pg, gamma, delta, 0);
        // q|k = g @ WT^T   (tensor tf32)
        launch_mgemm<EPI_STORE>(pg, pWT, pqk, QKW, D_, D_, D_, QKW, 0.f);
        // S[b,h] = q_h @ k_h^T   (fp32)
        {   GP p = { pqk, pqk + 768, pP, 0, NT, NT, Y_, NT,
                     QKW, 1, 1, QKW,
                     GB2, 64,  GB2, 64,  (long long)HEADS_ * PB2, PB2,
                     HEADS_, B_ * HEADS_, 0.f };
            launch_gemm<EPI_STORE>(p);
        }
        softmax_kernel<<<B_ * HEADS_ * NT, 128>>>(pP);
        // oq = P @ k_h   (fp32)
        {   GP p = { pP, pqk + 768, poqk, 0, NT, Y_, NT, QKW,
                     NT, 1, QKW, 1,
                     (long long)HEADS_ * PB2, PB2,  GB2, 64,  GB2, 64,
                     HEADS_, B_ * HEADS_, 0.f };
            launch_gemm<EPI_STORE>(p);
        }
        // ok = P^T @ q_h   (fp32)
        {   GP p = { pP, pqk, poqk + 768, 0, NT, Y_, NT, QKW,
                     1, NT, QKW, 1,
                     (long long)HEADS_ * PB2, PB2,  GB2, 64,  GB2, 64,
                     HEADS_, B_ * HEADS_, 0.f };
            launch_gemm<EPI_STORE>(p);
        }
        // x += alpha * [oq|ok] @ W2^T   (tensor tf32)
        launch_mgemm<EPI_AXPY>(poqk, pW2, px, D_, QKW, QKW, QKW, D_, ALPHA_);
        // Z = relu(g @ Xi)   (tensor tf32)
        launch_mgemm<EPI_RELU>(pg, pXiT, pZ, M_, D_, D_, D_, M_, 0.f);
        // x += alpha * Z @ Xi^T   (tensor tf32)
        launch_mgemm<EPI_AXPY>(pZ, Xi, px, D_, M_, M_, M_, D_, ALPHA_);
    }

    // decode
    lnorm_kernel<<<ROWSE, 256>>>(px, pg, gamma, delta, 1);
    {   GP p = { pg, dec_W, pdec, dec_b, ROWSE, D_, D_, D_,
                 D_, 1, D_, 1, 0,0,0,0,0,0, 1, 1, 0.f };
        launch_gemm<EPI_BIAS>(p);
    }
    unpatchify_kernel<<<(B_ * 3 * 224 * 224 + 255) / 256, 256>>>(pdec, out);
}

// round 4
// speedup vs baseline: 2.5962x; 1.2132x over previous
#include <cuda_runtime.h>
#include <cstdint>

#define B_      16
#define NP      196
#define NT      197
#define D_      768
#define M_      3072
#define HEADS_  12
#define Y_      64
#define NSTEPS_ 12
#define ALPHA_  0.1f
#define BETA_   0.125f
#define EPS_    1e-5f
#define NMASK_  100
#define RP      3200              // padded row count (25 * 128)
#define QKW     1536              // fused q|k width
#define KP      224               // padded token dim for P (7*32)
#define PSTR    (256*KP)          // per-(b,h) P slice stride in floats
#define NBH     (B_*HEADS_)       // 192

// ---------------- scratch (device globals; zero-initialized) ----------------
__device__ float d_patches[B_*NP*D_];
__device__ float d_tok[B_*NP*D_];
__device__ float d_x[RP*D_];
__device__ float d_g[RP*D_];
__device__ float d_qk[(RP+64)*QKW];
__device__ float d_oqk[RP*QKW];
__device__ float d_P[NBH*PSTR];
__device__ float d_PT[NBH*PSTR];
__device__ float d_Z[RP*M_];
__device__ float d_W2[D_*QKW];    // [d][hy|768+hy]  (tf32-rounded)
__device__ float d_WT[QKW*D_];    // [hy][d]         (tf32-rounded)
__device__ float d_XiR[D_*M_];    // rounded Xi
__device__ float d_XiT[M_*D_];    // rounded Xi^T
__device__ float d_dec[B_*NP*D_];

#define EPI_STORE   0
#define EPI_BIAS    1
#define EPI_RELU_T  2
#define EPI_AXPY    3
#define EPI_STORE_T 4

__device__ __forceinline__ uint32_t smem_u32(const void* p) {
    uint32_t a;
    asm("{ .reg .u64 t; cvta.to.shared.u64 t, %1; cvt.u32.u64 %0, t; }" : "=r"(a) : "l"(p));
    return a;
}
__device__ __forceinline__ float tf32r(float v) {
    uint32_t u;
    asm("cvt.rna.tf32.f32 %0, %1;" : "=r"(u) : "f"(v));
    return __uint_as_float(u);
}

// ---- tile loaders (cp.async, 16B chunks) ----
// A-style: 128 rows x 32 floats, smem stride 36
__device__ __forceinline__ void ldA32(float* s, const float* gp, int ld, int tid) {
    const float* grow = gp + (long long)tid * ld;
    uint32_t srow = smem_u32(s + tid * 36);
#pragma unroll
    for (int i = 0; i < 8; i++)
        asm volatile("cp.async.cg.shared.global [%0], [%1], 16;"
                     :: "r"(srow + i * 16), "l"(grow + i * 4));
}
// BN-style: 32 k-rows x 128 n-floats, smem stride 136
__device__ __forceinline__ void ldB32n(float* s, const float* gp, int ld, int tid) {
    int row = tid >> 2;
    int c0 = (tid & 3) * 32;
    const float* grow = gp + (long long)row * ld + c0;
    uint32_t srow = smem_u32(s + row * 136 + c0);
#pragma unroll
    for (int i = 0; i < 8; i++)
        asm volatile("cp.async.cg.shared.global [%0], [%1], 16;"
                     :: "r"(srow + i * 16), "l"(grow + i * 4));
}

// ================= unified tf32 mma.sync GEMM =================
// C[m,n] (op)= sum_k A[m,k]*B(k,n).
// BN=true : B stored row-major [K x N] (k rows, n contiguous)
// BN=false: B stored [N x K] row-major (k-major rows) i.e. B^T layout
// Block 128x128, K-chunk 32, 2-stage cp.async, 4 warps of 64x64.
template<int EPI, bool BN, bool GUARD>
__global__ __launch_bounds__(128, 2) void tmma_kernel(
    const float* __restrict__ A, const float* __restrict__ Bm,
    float* __restrict__ C, int K, int lda, int ldb, int ldc,
    long long oA0, long long oA1, long long oB0, long long oB1,
    long long oC0, long long oC1, int innerB,
    int Mv, int Nv, int Nz, float alpha)
{
    extern __shared__ float sm[];
    constexpr int ASZ = 128 * 36;
    constexpr int BSZ = BN ? 32 * 136 : 128 * 36;
    float* sA[2] = { sm, sm + ASZ + BSZ };
    float* sB[2] = { sm + ASZ, sm + 2 * ASZ + BSZ };

    int z = blockIdx.z;
    int zo = z / innerB, zi = z - zo * innerB;
    A  += zo * oA0 + zi * oA1;
    Bm += zo * oB0 + zi * oB1;
    C  += zo * oC0 + zi * oC1;

    const int tid = threadIdx.x;
    const int lane = tid & 31, wid = tid >> 5;
    const int grp = lane >> 2, tig = lane & 3;
    const int wm = (wid >> 1) * 64, wn = (wid & 1) * 64;
    const long long m0 = (long long)blockIdx.y * 128;
    const long long n0 = (long long)blockIdx.x * 128;
    A += m0 * lda;
    if (BN) Bm += n0;               // n offset into row-major [K x N]
    else    Bm += n0 * ldb;         // row offset into [N x K]

    float acc[4][8][4];
#pragma unroll
    for (int i = 0; i < 4; i++)
#pragma unroll
        for (int j = 0; j < 8; j++)
#pragma unroll
            for (int c = 0; c < 4; c++) acc[i][j][c] = 0.f;

    const int nk = K >> 5;

    // prefetch stage 0
    ldA32(sA[0], A, lda, tid);
    if (BN) ldB32n(sB[0], Bm, ldb, tid);
    else    ldA32(sB[0], Bm, ldb, tid);
    asm volatile("cp.async.commit_group;" ::: "memory");

    for (int kt = 0; kt < nk; kt++) {
        if (kt + 1 < nk) {
            int st = (kt + 1) & 1;
            ldA32(sA[st], A + (kt + 1) * 32, lda, tid);
            if (BN) ldB32n(sB[st], Bm + (long long)(kt + 1) * 32 * ldb, ldb, tid);
            else    ldA32(sB[st], Bm + (kt + 1) * 32, ldb, tid);
            asm volatile("cp.async.commit_group;" ::: "memory");
            asm volatile("cp.async.wait_group 1;" ::: "memory");
        } else {
            asm volatile("cp.async.wait_group 0;" ::: "memory");
        }
        __syncthreads();

        const float* cA = sA[kt & 1];
        const float* cB = sB[kt & 1];
#pragma unroll
        for (int kk = 0; kk < 32; kk += 8) {
            uint32_t af[4][4], bf[8][2];
#pragma unroll
            for (int mt = 0; mt < 4; mt++) {
                const float* p = cA + (wm + mt * 16 + grp) * 36 + kk + tig;
                af[mt][0] = __float_as_uint(p[0]);
                af[mt][1] = __float_as_uint(p[8 * 36]);
                af[mt][2] = __float_as_uint(p[4]);
                af[mt][3] = __float_as_uint(p[8 * 36 + 4]);
            }
#pragma unroll
            for (int nt = 0; nt < 8; nt++) {
                if (BN) {
                    const float* p = cB + (kk + tig) * 136 + wn + nt * 8 + grp;
                    bf[nt][0] = __float_as_uint(p[0]);
                    bf[nt][1] = __float_as_uint(p[4 * 136]);
                } else {
                    const float* p = cB + (wn + nt * 8 + grp) * 36 + kk + tig;
                    bf[nt][0] = __float_as_uint(p[0]);
                    bf[nt][1] = __float_as_uint(p[4]);
                }
            }
#pragma unroll
            for (int mt = 0; mt < 4; mt++)
#pragma unroll
                for (int nt = 0; nt < 8; nt++) {
                    asm("mma.sync.aligned.m16n8k8.row.col.f32.tf32.tf32.f32 "
                        "{%0,%1,%2,%3}, {%4,%5,%6,%7}, {%8,%9}, {%0,%1,%2,%3};"
                        : "+f"(acc[mt][nt][0]), "+f"(acc[mt][nt][1]),
                          "+f"(acc[mt][nt][2]), "+f"(acc[mt][nt][3])
                        : "r"(af[mt][0]), "r"(af[mt][1]), "r"(af[mt][2]), "r"(af[mt][3]),
                          "r"(bf[nt][0]), "r"(bf[nt][1]));
                }
        }
        __syncthreads();
    }

    // ---- epilogue ----
    if (GUARD) {
#pragma unroll
        for (int mt = 0; mt < 4; mt++) {
            long long r0 = m0 + wm + mt * 16 + grp;
            long long r1 = r0 + 8;
#pragma unroll
            for (int nt = 0; nt < 8; nt++) {
                long long c = n0 + wn + nt * 8 + 2 * tig;
#pragma unroll
                for (int e = 0; e < 4; e++) {
                    long long r = (e < 2) ? r0 : r1;
                    long long cc = c + (e & 1);
                    float v = acc[mt][nt][e];
                    if (r < Mv) {
                        if (cc < Nv) {
                            float* p = C + r * ldc + cc;
                            if (EPI == EPI_RELU_T) v = tf32r(fmaxf(v, 0.f));
                            if (EPI == EPI_STORE_T) v = tf32r(v);
                            if (EPI == EPI_AXPY) v = *p + alpha * v;
                            *p = v;
                        } else if (cc < Nz) {
                            C[r * ldc + cc] = 0.f;
                        }
                    }
                }
            }
        }
    } else {
#pragma unroll
        for (int mt = 0; mt < 4; mt++) {
            long long r0 = m0 + wm + mt * 16 + grp;
            float* c0 = C + r0 * ldc + n0 + wn;
            float* c1 = c0 + 8LL * ldc;
#pragma unroll
            for (int nt = 0; nt < 8; nt++) {
                int col = nt * 8 + 2 * tig;
                float2 v0 = make_float2(acc[mt][nt][0], acc[mt][nt][1]);
                float2 v1 = make_float2(acc[mt][nt][2], acc[mt][nt][3]);
                if (EPI == EPI_RELU_T) {
                    v0.x = tf32r(fmaxf(v0.x, 0.f)); v0.y = tf32r(fmaxf(v0.y, 0.f));
                    v1.x = tf32r(fmaxf(v1.x, 0.f)); v1.y = tf32r(fmaxf(v1.y, 0.f));
                }
                if (EPI == EPI_STORE_T) {
                    v0.x = tf32r(v0.x); v0.y = tf32r(v0.y);
                    v1.x = tf32r(v1.x); v1.y = tf32r(v1.y);
                }
                if (EPI == EPI_AXPY) {
                    float2 o0 = *(float2*)(c0 + col);
                    float2 o1 = *(float2*)(c1 + col);
                    v0.x = o0.x + alpha * v0.x; v0.y = o0.y + alpha * v0.y;
                    v1.x = o1.x + alpha * v1.x; v1.y = o1.y + alpha * v1.y;
                }
                *(float2*)(c0 + col) = v0;
                *(float2*)(c1 + col) = v1;
            }
        }
    }
}

// ================= fp32 SGEMM (encode/decode only) =================
template<int EPI>
__global__ void __launch_bounds__(256, 2) gemm_kernel(
    const float* __restrict__ A, const float* __restrict__ B,
    float* __restrict__ C, const float* __restrict__ bias,
    int M, int N, int K, int ldc, int sAm, int sAk, int sBk, int sBn)
{
    __shared__ float As[8][128];
    __shared__ float Bs[8][128];
    int row0 = blockIdx.y * 128;
    int col0 = blockIdx.x * 128;
    int tid  = threadIdx.x;
    int lrow = tid >> 1;
    int lk4  = (tid & 1) * 4;
    int tx   = (tid & 15) * 8;
    int ty   = (tid >> 4) * 8;

    float acc[8][8];
#pragma unroll
    for (int i = 0; i < 8; i++)
#pragma unroll
        for (int j = 0; j < 8; j++) acc[i][j] = 0.f;

    for (int k0 = 0; k0 < K; k0 += 8) {
        int m = row0 + lrow;
#pragma unroll
        for (int i = 0; i < 4; i++) {
            int kk = k0 + lk4 + i;
            float v = 0.f;
            if (m < M && kk < K) v = A[(long long)m * sAm + (long long)kk * sAk];
            As[lk4 + i][lrow] = v;
        }
        int n = col0 + lrow;
#pragma unroll
        for (int i = 0; i < 4; i++) {
            int kk = k0 + lk4 + i;
            float v = 0.f;
            if (n < N && kk < K) v = B[(long long)kk * sBk + (long long)n * sBn];
            Bs[lk4 + i][lrow] = v;
        }
        __syncthreads();
#pragma unroll
        for (int kk = 0; kk < 8; kk++) {
            float a[8], b[8];
#pragma unroll
            for (int i = 0; i < 8; i++) a[i] = As[kk][ty + i];
#pragma unroll
            for (int j = 0; j < 8; j++) b[j] = Bs[kk][tx + j];
#pragma unroll
            for (int i = 0; i < 8; i++)
#pragma unroll
                for (int j = 0; j < 8; j++) acc[i][j] += a[i] * b[j];
        }
        __syncthreads();
    }
#pragma unroll
    for (int i = 0; i < 8; i++) {
        int m = row0 + ty + i;
        if (m < M) {
            float* crow = C + (long long)m * ldc;
#pragma unroll
            for (int j = 0; j < 8; j++) {
                int n = col0 + tx + j;
                if (n < N) {
                    float v = acc[i][j];
                    if (EPI == EPI_BIAS) v += bias[n];
                    crow[n] = v;
                }
            }
        }
    }
}

// ================= layernorm =================
__device__ __forceinline__ float block_sum256(float v, float* red) {
    int lane = threadIdx.x & 31, w = threadIdx.x >> 5;
#pragma unroll
    for (int o = 16; o > 0; o >>= 1) v += __shfl_xor_sync(0xffffffffu, v, o);
    if (lane == 0) red[w] = v;
    __syncthreads();
    float s = 0.f;
#pragma unroll
    for (int i = 0; i < 8; i++) s += red[i];
    __syncthreads();
    return s;
}

__global__ void lnorm_kernel(const float* __restrict__ x, float* __restrict__ g,
                             const float* __restrict__ gamma_p,
                             const float* __restrict__ delta, int skipcls, int roundout)
{
    __shared__ float red[8];
    int r = blockIdx.x;
    const float* xr;
    float* gr;
    if (skipcls) {
        int b = r / NP, i = r - b * NP;
        xr = x + (long long)(b * NT + 1 + i) * D_;
        gr = g + (long long)r * D_;
    } else {
        xr = x + (long long)r * D_;
        gr = g + (long long)r * D_;
    }
    int t = threadIdx.x; // 256
    float v0 = xr[t], v1 = xr[t + 256], v2 = xr[t + 512];
    float mean = block_sum256(v0 + v1 + v2, red) * (1.f / 768.f);
    float c0 = v0 - mean, c1 = v1 - mean, c2 = v2 - mean;
    float var = block_sum256(c0*c0 + c1*c1 + c2*c2, red) * (1.f / 768.f);
    float rinv = rsqrtf(var + EPS_);
    float gm = gamma_p[0];
    float o0 = gm * c0 * rinv + delta[t];
    float o1 = gm * c1 * rinv + delta[t + 256];
    float o2 = gm * c2 * rinv + delta[t + 512];
    if (roundout) { o0 = tf32r(o0); o1 = tf32r(o1); o2 = tf32r(o2); }
    gr[t] = o0; gr[t + 256] = o1; gr[t + 512] = o2;
}

// ================= softmax (padded P, rounds output) =================
__global__ void softmax_kernel(float* __restrict__ P)
{
    __shared__ float red[4];
    int blk = blockIdx.x;
    int z = blk / NT, r = blk - z * NT;
    float* p = P + (long long)z * PSTR + (long long)r * KP;
    int t = threadIdx.x;          // 128
    int lane = t & 31, w = t >> 5;
    float a0 = (t < NT)       ? p[t]       : -1e30f;
    float a1 = (t + 128 < NT) ? p[t + 128] : -1e30f;
    float mx = fmaxf(a0, a1);
#pragma unroll
    for (int o = 16; o > 0; o >>= 1) mx = fmaxf(mx, __shfl_xor_sync(0xffffffffu, mx, o));
    if (lane == 0) red[w] = mx;
    __syncthreads();
    mx = fmaxf(fmaxf(red[0], red[1]), fmaxf(red[2], red[3]));
    __syncthreads();
    float e0 = (t < NT)       ? expf(BETA_ * (a0 - mx)) : 0.f;
    float e1 = (t + 128 < NT) ? expf(BETA_ * (a1 - mx)) : 0.f;
    float s = e0 + e1;
#pragma unroll
    for (int o = 16; o > 0; o >>= 1) s += __shfl_xor_sync(0xffffffffu, s, o);
    if (lane == 0) red[w] = s;
    __syncthreads();
    s = red[0] + red[1] + red[2] + red[3];
    float inv = 1.f / s;
    if (t < NT)       p[t]       = tf32r(e0 * inv);
    if (t + 128 < NT) p[t + 128] = tf32r(e1 * inv);
}

// ================= P transpose (zero-fills k>=197) =================
__global__ void transpose_p_kernel(const float* __restrict__ P, float* __restrict__ PT)
{
    __shared__ float t[32][33];
    int z = blockIdx.z;
    int k0 = blockIdx.y * 32, m0 = blockIdx.x * 32;
    const float* p = P + (long long)z * PSTR;
    float* q = PT + (long long)z * PSTR;
    int tx = threadIdx.x & 31, ty = threadIdx.x >> 5;  // 256 threads = 32x8
#pragma unroll
    for (int i = 0; i < 32; i += 8)
        t[ty + i][tx] = p[(long long)(k0 + ty + i) * KP + m0 + tx];
    __syncthreads();
#pragma unroll
    for (int i = 0; i < 32; i += 8) {
        int m = m0 + ty + i, k = k0 + tx;
        q[(long long)m * KP + k] = (k < NT) ? t[tx][ty + i] : 0.f;
    }
}

// ================= weight prep =================
__global__ void build_wqk_kernel(const float* __restrict__ Wq, const float* __restrict__ Wk,
                                 float* __restrict__ W2, float* __restrict__ WT)
{
    int idx = blockIdx.x * 256 + threadIdx.x;
    if (idx >= 2 * D_ * D_) return;
    int which = idx >= D_ * D_;
    int r = idx - which * D_ * D_;
    int h = r / (D_ * Y_);
    int rem = r - h * (D_ * Y_);
    int d = rem / Y_;
    int y = rem - d * Y_;
    float v = tf32r(which ? Wk[r] : Wq[r]);
    int hy = h * Y_ + y + which * D_;
    W2[d * QKW + hy] = v;
    WT[(long long)hy * D_ + d] = v;
}

__global__ void build_xi_kernel(const float* __restrict__ Xi,
                                float* __restrict__ XiR, float* __restrict__ XiT)
{
    __shared__ float t[32][33];
    int d0 = blockIdx.y * 32, m0 = blockIdx.x * 32;
    int tx = threadIdx.x & 31, ty = threadIdx.x >> 5;  // 256 threads
#pragma unroll
    for (int i = 0; i < 32; i += 8) {
        float v = tf32r(Xi[(long long)(d0 + ty + i) * M_ + m0 + tx]);
        XiR[(long long)(d0 + ty + i) * M_ + m0 + tx] = v;
        t[ty + i][tx] = v;
    }
    __syncthreads();
#pragma unroll
    for (int i = 0; i < 32; i += 8)
        XiT[(long long)(m0 + ty + i) * D_ + d0 + tx] = t[tx][ty + i];
}

// ================= misc =================
__global__ void patchify_kernel(const float* __restrict__ img, float* __restrict__ out)
{
    int idx = blockIdx.x * 256 + threadIdx.x;
    if (idx >= B_ * NP * D_) return;
    int e = idx % D_;
    int rest = idx / D_;
    int p = rest % NP;
    int b = rest / NP;
    int c = e >> 8;
    int r = (e >> 4) & 15;
    int col = e & 15;
    int kh = p / 14, kw = p - kh * 14;
    out[idx] = img[((long long)(b * 3 + c) * 224 + kh * 16 + r) * 224 + kw * 16 + col];
}

__global__ void unpatchify_kernel(const float* __restrict__ dec, float* __restrict__ out)
{
    int idx = blockIdx.x * 256 + threadIdx.x;
    if (idx >= B_ * 3 * 224 * 224) return;
    int w = idx % 224;
    int rest = idx / 224;
    int h = rest % 224;
    rest /= 224;
    int c = rest % 3;
    int b = rest / 3;
    int kh = h >> 4, r = h & 15, kw = w >> 4, col = w & 15;
    out[idx] = dec[(long long)(b * NP + kh * 14 + kw) * D_ + c * 256 + r * 16 + col];
}

__global__ void build_x_kernel(const float* __restrict__ tok, const int* __restrict__ mask,
                               const float* __restrict__ cls, const float* __restrict__ mtok,
                               const float* __restrict__ pos, float* __restrict__ x)
{
    __shared__ int sm[NP];
    __shared__ unsigned char flag[NP];
    __shared__ int count_s;
    int b = blockIdx.x;
    int t = threadIdx.x; // 256
    if (t < NP) sm[t] = mask[b * NP + t];
    __syncthreads();
    if (t < NP) {
        int pref = 0;
        for (int j = 0; j < t; j++) pref += (sm[j] == 1);
        flag[t] = (sm[t] == 1 && pref < NMASK_) ? 1 : 0;
        if (t == NP - 1) count_s = pref + (sm[t] == 1);
    }
    __syncthreads();
    if (t == 0 && count_s < NMASK_) flag[0] = 1; // fill_value=0 padding hits token 0
    __syncthreads();
    for (int tk = 0; tk < NT; tk++) {
        const float* src;
        if (tk == 0) src = cls;
        else if (flag[tk - 1]) src = mtok;
        else src = tok + (long long)(b * NP + tk - 1) * D_;
        float* dst = x + (long long)(b * NT + tk) * D_;
        const float* pr = pos + (long long)tk * D_;
        for (int d = t; d < D_; d += 256) dst[d] = src[d] + pr[d];
    }
}

// ================= host wrappers =================
template<int EPI, bool BN, bool GUARD>
static void launch_t(const float* A, const float* B, float* C,
                     int Mtiles, int Ntiles, int batch, int K,
                     int lda, int ldb, int ldc,
                     long long oA0, long long oA1, long long oB0, long long oB1,
                     long long oC0, long long oC1, int innerB,
                     int Mv, int Nv, int Nz, float alpha)
{
    constexpr int ASZ = 128 * 36;
    constexpr int BSZ = BN ? 32 * 136 : 128 * 36;
    int smem = 2 * (ASZ + BSZ) * 4;
    cudaFuncSetAttribute(tmma_kernel<EPI, BN, GUARD>,
                         cudaFuncAttributeMaxDynamicSharedMemorySize, smem);
    dim3 g(Ntiles, Mtiles, batch);
    tmma_kernel<EPI, BN, GUARD><<<g, 128, smem>>>(A, B, C, K, lda, ldb, ldc,
        oA0, oA1, oB0, oB1, oC0, oC1, innerB, Mv, Nv, Nz, alpha);
}

extern "C" void kernel_launch(void* const* d_in, const int* in_sizes, int n_in,
                              void* d_out, int out_size)
{
    const float* img   = (const float*)d_in[0];
    const int*   mask  = (const int*)  d_in[1];
    const float* enc_W = (const float*)d_in[2];
    const float* enc_b = (const float*)d_in[3];
    const float* dec_W = (const float*)d_in[4];
    const float* dec_b = (const float*)d_in[5];
    const float* cls   = (const float*)d_in[6];
    const float* mtok  = (const float*)d_in[7];
    const float* pos   = (const float*)d_in[8];
    const float* Wq    = (const float*)d_in[9];
    const float* Wk    = (const float*)d_in[10];
    const float* Xi    = (const float*)d_in[11];
    const float* gamma = (const float*)d_in[12];
    const float* delta = (const float*)d_in[13];
    float* out = (float*)d_out;

    float *ppat, *ptok, *px, *pg, *pqk, *poqk, *pP, *pPT, *pZ, *pW2, *pWT, *pXiR, *pXiT, *pdec;
    cudaGetSymbolAddress((void**)&ppat, d_patches);
    cudaGetSymbolAddress((void**)&ptok, d_tok);
    cudaGetSymbolAddress((void**)&px,   d_x);
    cudaGetSymbolAddress((void**)&pg,   d_g);
    cudaGetSymbolAddress((void**)&pqk,  d_qk);
    cudaGetSymbolAddress((void**)&poqk, d_oqk);
    cudaGetSymbolAddress((void**)&pP,   d_P);
    cudaGetSymbolAddress((void**)&pPT,  d_PT);
    cudaGetSymbolAddress((void**)&pZ,   d_Z);
    cudaGetSymbolAddress((void**)&pW2,  d_W2);
    cudaGetSymbolAddress((void**)&pWT,  d_WT);
    cudaGetSymbolAddress((void**)&pXiR, d_XiR);
    cudaGetSymbolAddress((void**)&pXiT, d_XiT);
    cudaGetSymbolAddress((void**)&pdec, d_dec);

    const int ROWS  = B_ * NT;   // 3152
    const int ROWSE = B_ * NP;   // 3136
    const long long GB2 = (long long)NT * QKW;   // per-batch token block in qk/oqk

    // weight prep
    build_wqk_kernel<<<(2 * D_ * D_ + 255) / 256, 256>>>(Wq, Wk, pW2, pWT);
    build_xi_kernel<<<dim3(M_ / 32, D_ / 32), 256>>>(Xi, pXiR, pXiT);

    // encode (fp32)
    patchify_kernel<<<(B_ * NP * D_ + 255) / 256, 256>>>(img, ppat);
    gemm_kernel<EPI_BIAS><<<dim3(6, 25), 256>>>(ppat, enc_W, ptok, enc_b,
        ROWSE, D_, D_, D_, D_, 1, D_, 1);
    build_x_kernel<<<B_, 256>>>(ptok, mask, cls, mtok, pos, px);

    for (int s = 0; s < NSTEPS_; s++) {
        lnorm_kernel<<<ROWS, 256>>>(px, pg, gamma, delta, 0, 1);
        // q|k = g @ W2 (BN, rounds output)
        launch_t<EPI_STORE_T, true, false>(pg, pW2, pqk,
            25, 12, 1, D_, D_, QKW, QKW, 0,0,0,0,0,0, 1, 0,0,0, 0.f);
        // S = q @ k^T  (BT, guarded, zero-pads cols [197,224))
        launch_t<EPI_STORE, false, true>(pqk, pqk + 768, pP,
            2, 2, NBH, Y_, QKW, QKW, KP,
            GB2, 64, GB2, 64, (long long)HEADS_ * PSTR, PSTR, HEADS_,
            NT, NT, KP, 0.f);
        softmax_kernel<<<NBH * NT, 128>>>(pP);
        transpose_p_kernel<<<dim3(KP / 32, KP / 32, NBH), 256>>>(pP, pPT);
        // oq = P @ k  (BN, guarded, rounds)
        launch_t<EPI_STORE_T, true, true>(pP, pqk + 768, poqk,
            2, 1, NBH, KP, KP, QKW, QKW,
            (long long)HEADS_ * PSTR, PSTR, GB2, 64, GB2, 64, HEADS_,
            NT, Y_, Y_, 0.f);
        // ok = P^T @ q  (BN, guarded, rounds)
        launch_t<EPI_STORE_T, true, true>(pPT, pqk, poqk + 768,
            2, 1, NBH, KP, KP, QKW, QKW,
            (long long)HEADS_ * PSTR, PSTR, GB2, 64, GB2, 64, HEADS_,
            NT, Y_, Y_, 0.f);
        // x += alpha * [oq|ok] @ WT (BN)
        launch_t<EPI_AXPY, true, false>(poqk, pWT, px,
            25, 6, 1, QKW, QKW, D_, D_, 0,0,0,0,0,0, 1, 0,0,0, ALPHA_);
        // Z = relu(g @ Xi) (BN, rounds)
        launch_t<EPI_RELU_T, true, false>(pg, pXiR, pZ,
            25, 24, 1, D_, D_, M_, M_, 0,0,0,0,0,0, 1, 0,0,0, 0.f);
        // x += alpha * Z @ XiT (BN)
        launch_t<EPI_AXPY, true, false>(pZ, pXiT, px,
            25, 6, 1, M_, M_, D_, D_, 0,0,0,0,0,0, 1, 0,0,0, ALPHA_);
    }

    // decode (fp32)
    lnorm_kernel<<<ROWSE, 256>>>(px, pg, gamma, delta, 1, 0);
    gemm_kernel<EPI_BIAS><<<dim3(6, 25), 256>>>(pg, dec_W, pdec, dec_b,
        ROWSE, D_, D_, D_, D_, 1, D_, 1);
    unpatchify_kernel<<<(B_ * 3 * 224 * 224 + 255) / 256, 256>>>(pdec, out);
}

// round 5
// speedup vs baseline: 2.6845x; 1.0340x over previous
#include <cuda_runtime.h>
#include <cstdint>

#define B_      16
#define NP      196
#define NT      197
#define D_      768
#define M_      3072
#define HEADS_  12
#define Y_      64
#define NSTEPS_ 12
#define ALPHA_  0.1f
#define BETA_   0.125f
#define EPS_    1e-5f
#define NMASK_  100
#define RP      3200              // padded row count (25 * 128)
#define QKW     1536              // fused q|k width
#define KP      224               // padded token dim for P (7*32)
#define PSTR    (256*KP)          // per-(b,h) P slice stride in floats
#define NBH     (B_*HEADS_)       // 192

// ---------------- scratch (device globals) ----------------
__device__ float d_patches[RP*D_];
__device__ float d_tok[B_*NP*D_];
__device__ float d_x[RP*D_];
__device__ float d_g[RP*D_];
__device__ float d_qk[(RP+64)*QKW];
__device__ float d_oqk[RP*QKW];
__device__ float d_P[NBH*PSTR];
__device__ float d_PT[NBH*PSTR];
__device__ float d_Z[RP*M_];
__device__ float d_W2[D_*QKW];    // [d][hy|768+hy]  (rounded)  B for backproj (BT: N=d,K=hy)
__device__ float d_WT[QKW*D_];    // [hy][d]         (rounded)  B for proj (BT: N=hy,K=d)
__device__ float d_XiR[D_*M_];    // rounded Xi                 B for hopfield bwd (BT: N=d,K=mu)
__device__ float d_XiT[M_*D_];    // rounded Xi^T               B for hopfield fwd (BT: N=mu,K=d)
__device__ float d_encT[D_*D_];   // enc_W^T rounded
__device__ float d_decT[D_*D_];   // dec_W^T rounded
__device__ float d_dec[B_*NP*D_];

#define EPI_STORE   0
#define EPI_BIAS    1
#define EPI_RELU_T  2
#define EPI_AXPY    3
#define EPI_STORE_T 4

__device__ __forceinline__ uint32_t smem_u32(const void* p) {
    uint32_t a;
    asm("{ .reg .u64 t; cvta.to.shared.u64 t, %1; cvt.u32.u64 %0, t; }" : "=r"(a) : "l"(p));
    return a;
}
__device__ __forceinline__ float tf32r(float v) {
    uint32_t u;
    asm("cvt.rna.tf32.f32 %0, %1;" : "=r"(u) : "f"(v));
    return __uint_as_float(u);
}
__device__ __forceinline__ void ldsm4(uint32_t* r, uint32_t addr) {
    asm volatile("ldmatrix.sync.aligned.m8n8.x4.shared.b16 {%0,%1,%2,%3}, [%4];"
        : "=r"(r[0]), "=r"(r[1]), "=r"(r[2]), "=r"(r[3]) : "r"(addr));
}

// ---- tile loaders (cp.async, 16B chunks) ----
// k-major: 128 rows x 32 floats, smem stride 36 (144B, 16B-multiple for ldmatrix)
__device__ __forceinline__ void ldA32(float* s, const float* gp, int ld, int tid) {
    const float* grow = gp + (long long)tid * ld;
    uint32_t srow = smem_u32(s + tid * 36);
#pragma unroll
    for (int i = 0; i < 8; i++)
        asm volatile("cp.async.cg.shared.global [%0], [%1], 16;"
                     :: "r"(srow + i * 16), "l"(grow + i * 4));
}
// BN-style: 32 k-rows x 128 n-floats, smem stride 136
__device__ __forceinline__ void ldB32n(float* s, const float* gp, int ld, int tid) {
    int row = tid >> 2;
    int c0 = (tid & 3) * 32;
    const float* grow = gp + (long long)row * ld + c0;
    uint32_t srow = smem_u32(s + row * 136 + c0);
#pragma unroll
    for (int i = 0; i < 8; i++)
        asm volatile("cp.async.cg.shared.global [%0], [%1], 16;"
                     :: "r"(srow + i * 16), "l"(grow + i * 4));
}

// ================= BT tf32 mma GEMM with ldmatrix fragment loads =================
// C[m,n] (op)= sum_k A[m,k]*B[n,k];  A: [M x K] lda, B: [N x K] ldb (both k-major).
// Block 128x128, K-chunk 32, 2-stage cp.async, 4 warps of 64x64.
template<int EPI, bool GUARD>
__global__ __launch_bounds__(128, 2) void tbt_kernel(
    const float* __restrict__ A, const float* __restrict__ Bm,
    float* __restrict__ C, const float* __restrict__ bias,
    int K, int lda, int ldb, int ldc,
    long long oA0, long long oA1, long long oB0, long long oB1,
    long long oC0, long long oC1, int innerB,
    int Mv, int Nv, int Nz, float alpha)
{
    extern __shared__ float sm[];
    constexpr int TSZ = 128 * 36;
    float* sA[2] = { sm,           sm + 2 * TSZ };
    float* sB[2] = { sm + TSZ,     sm + 3 * TSZ };

    int z = blockIdx.z;
    int zo = z / innerB, zi = z - zo * innerB;
    A  += zo * oA0 + zi * oA1;
    Bm += zo * oB0 + zi * oB1;
    C  += zo * oC0 + zi * oC1;

    const int tid = threadIdx.x;
    const int lane = tid & 31, wid = tid >> 5;
    const int grp = lane >> 2, tig = lane & 3;
    const int wm = (wid >> 1) * 64, wn = (wid & 1) * 64;
    const long long m0 = (long long)blockIdx.y * 128;
    const long long n0 = (long long)blockIdx.x * 128;
    A += m0 * lda;
    Bm += n0 * ldb;

    // ldmatrix per-lane address offset: row = (lane&7) + ((lane>>3)&1)*8, khalf = lane>>4
    const uint32_t laneoff = ((lane & 7) + ((lane >> 3) & 1) * 8) * 144 + (lane >> 4) * 16;

    float acc[4][8][4];
#pragma unroll
    for (int i = 0; i < 4; i++)
#pragma unroll
        for (int j = 0; j < 8; j++)
#pragma unroll
            for (int c = 0; c < 4; c++) acc[i][j][c] = 0.f;

    const int nk = K >> 5;
    ldA32(sA[0], A, lda, tid);
    ldA32(sB[0], Bm, ldb, tid);
    asm volatile("cp.async.commit_group;" ::: "memory");

    for (int kt = 0; kt < nk; kt++) {
        if (kt + 1 < nk) {
            int st = (kt + 1) & 1;
            ldA32(sA[st], A + (kt + 1) * 32, lda, tid);
            ldA32(sB[st], Bm + (kt + 1) * 32, ldb, tid);
            asm volatile("cp.async.commit_group;" ::: "memory");
            asm volatile("cp.async.wait_group 1;" ::: "memory");
        } else {
            asm volatile("cp.async.wait_group 0;" ::: "memory");
        }
        __syncthreads();

        const uint32_t aBase = smem_u32(sA[kt & 1]) + wm * 144 + laneoff;
        const uint32_t bBase = smem_u32(sB[kt & 1]) + wn * 144 + laneoff;
#pragma unroll
        for (int kk = 0; kk < 32; kk += 8) {
            uint32_t af[4][4], bp[4][4];
#pragma unroll
            for (int mt = 0; mt < 4; mt++)
                ldsm4(af[mt], aBase + mt * 16 * 144 + kk * 4);
#pragma unroll
            for (int nb = 0; nb < 4; nb++)
                ldsm4(bp[nb], bBase + nb * 16 * 144 + kk * 4);
#pragma unroll
            for (int mt = 0; mt < 4; mt++)
#pragma unroll
                for (int nt = 0; nt < 8; nt++) {
                    asm("mma.sync.aligned.m16n8k8.row.col.f32.tf32.tf32.f32 "
                        "{%0,%1,%2,%3}, {%4,%5,%6,%7}, {%8,%9}, {%0,%1,%2,%3};"
                        : "+f"(acc[mt][nt][0]), "+f"(acc[mt][nt][1]),
                          "+f"(acc[mt][nt][2]), "+f"(acc[mt][nt][3])
                        : "r"(af[mt][0]), "r"(af[mt][1]), "r"(af[mt][2]), "r"(af[mt][3]),
                          "r"(bp[nt >> 1][nt & 1]), "r"(bp[nt >> 1][2 + (nt & 1)]));
                }
        }
        __syncthreads();
    }

    // ---- epilogue ----
    if (GUARD) {
#pragma unroll
        for (int mt = 0; mt < 4; mt++) {
            long long r0 = m0 + wm + mt * 16 + grp;
            long long r1 = r0 + 8;
#pragma unroll
            for (int nt = 0; nt < 8; nt++) {
                long long c = n0 + wn + nt * 8 + 2 * tig;
#pragma unroll
                for (int e = 0; e < 4; e++) {
                    long long r = (e < 2) ? r0 : r1;
                    long long cc = c + (e & 1);
                    float v = acc[mt][nt][e];
                    if (r < Mv) {
                        if (cc < Nv) {
                            float* p = C + r * ldc + cc;
                            if (EPI == EPI_RELU_T) v = tf32r(fmaxf(v, 0.f));
                            if (EPI == EPI_STORE_T) v = tf32r(v);
                            if (EPI == EPI_BIAS) v += bias[cc];
                            if (EPI == EPI_AXPY) v = *p + alpha * v;
                            *p = v;
                        } else if (cc < Nz) {
                            C[r * ldc + cc] = 0.f;
                        }
                    }
                }
            }
        }
    } else {
#pragma unroll
        for (int mt = 0; mt < 4; mt++) {
            long long r0 = m0 + wm + mt * 16 + grp;
            float* c0 = C + r0 * ldc + n0 + wn;
            float* c1 = c0 + 8LL * ldc;
#pragma unroll
            for (int nt = 0; nt < 8; nt++) {
                int col = nt * 8 + 2 * tig;
                float2 v0 = make_float2(acc[mt][nt][0], acc[mt][nt][1]);
                float2 v1 = make_float2(acc[mt][nt][2], acc[mt][nt][3]);
                if (EPI == EPI_RELU_T) {
                    v0.x = tf32r(fmaxf(v0.x, 0.f)); v0.y = tf32r(fmaxf(v0.y, 0.f));
                    v1.x = tf32r(fmaxf(v1.x, 0.f)); v1.y = tf32r(fmaxf(v1.y, 0.f));
                }
                if (EPI == EPI_STORE_T) {
                    v0.x = tf32r(v0.x); v0.y = tf32r(v0.y);
                    v1.x = tf32r(v1.x); v1.y = tf32r(v1.y);
                }
                if (EPI == EPI_AXPY) {
                    float2 o0 = *(float2*)(c0 + col);
                    float2 o1 = *(float2*)(c1 + col);
                    v0.x = o0.x + alpha * v0.x; v0.y = o0.y + alpha * v0.y;
                    v1.x = o1.x + alpha * v1.x; v1.y = o1.y + alpha * v1.y;
                }
                *(float2*)(c0 + col) = v0;
                *(float2*)(c1 + col) = v1;
            }
        }
    }
}

// ================= BN tf32 mma GEMM (oq/ok only: B row-major [K x N]) =================
template<int EPI>
__global__ __launch_bounds__(128, 2) void tbn_kernel(
    const float* __restrict__ A, const float* __restrict__ Bm,
    float* __restrict__ C, int K, int lda, int ldb, int ldc,
    long long oA0, long long oA1, long long oB0, long long oB1,
    long long oC0, long long oC1, int innerB,
    int Mv, int Nv, float alpha)
{
    extern __shared__ float sm[];
    constexpr int ASZ = 128 * 36;
    constexpr int BSZ = 32 * 136;
    float* sA[2] = { sm, sm + ASZ + BSZ };
    float* sB[2] = { sm + ASZ, sm + 2 * ASZ + BSZ };

    int z = blockIdx.z;
    int zo = z / innerB, zi = z - zo * innerB;
    A  += zo * oA0 + zi * oA1;
    Bm += zo * oB0 + zi * oB1;
    C  += zo * oC0 + zi * oC1;

    const int tid = threadIdx.x;
    const int lane = tid & 31, wid = tid >> 5;
    const int grp = lane >> 2, tig = lane & 3;
    const int wm = (wid >> 1) * 64, wn = (wid & 1) * 64;
    const long long m0 = (long long)blockIdx.y * 128;
    const long long n0 = (long long)blockIdx.x * 128;
    A += m0 * lda;
    Bm += n0;

    const uint32_t laneoff = ((lane & 7) + ((lane >> 3) & 1) * 8) * 144 + (lane >> 4) * 16;

    float acc[4][8][4];
#pragma unroll
    for (int i = 0; i < 4; i++)
#pragma unroll
        for (int j = 0; j < 8; j++)
#pragma unroll
            for (int c = 0; c < 4; c++) acc[i][j][c] = 0.f;

    const int nk = K >> 5;
    ldA32(sA[0], A, lda, tid);
    ldB32n(sB[0], Bm, ldb, tid);
    asm volatile("cp.async.commit_group;" ::: "memory");

    for (int kt = 0; kt < nk; kt++) {
        if (kt + 1 < nk) {
            int st = (kt + 1) & 1;
            ldA32(sA[st], A + (kt + 1) * 32, lda, tid);
            ldB32n(sB[st], Bm + (long long)(kt + 1) * 32 * ldb, ldb, tid);
            asm volatile("cp.async.commit_group;" ::: "memory");
            asm volatile("cp.async.wait_group 1;" ::: "memory");
        } else {
            asm volatile("cp.async.wait_group 0;" ::: "memory");
        }
        __syncthreads();

        const uint32_t aBase = smem_u32(sA[kt & 1]) + wm * 144 + laneoff;
        const float* cB = sB[kt & 1];
#pragma unroll
        for (int kk = 0; kk < 32; kk += 8) {
            uint32_t af[4][4], bf[8][2];
#pragma unroll
            for (int mt = 0; mt < 4; mt++)
                ldsm4(af[mt], aBase + mt * 16 * 144 + kk * 4);
#pragma unroll
            for (int nt = 0; nt < 8; nt++) {
                const float* p = cB + (kk + tig) * 136 + wn + nt * 8 + grp;
                bf[nt][0] = __float_as_uint(p[0]);
                bf[nt][1] = __float_as_uint(p[4 * 136]);
            }
#pragma unroll
            for (int mt = 0; mt < 4; mt++)
#pragma unroll
                for (int nt = 0; nt < 8; nt++) {
                    asm("mma.sync.aligned.m16n8k8.row.col.f32.tf32.tf32.f32 "
                        "{%0,%1,%2,%3}, {%4,%5,%6,%7}, {%8,%9}, {%0,%1,%2,%3};"
                        : "+f"(acc[mt][nt][0]), "+f"(acc[mt][nt][1]),
                          "+f"(acc[mt][nt][2]), "+f"(acc[mt][nt][3])
                        : "r"(af[mt][0]), "r"(af[mt][1]), "r"(af[mt][2]), "r"(af[mt][3]),
                          "r"(bf[nt][0]), "r"(bf[nt][1]));
                }
        }
        __syncthreads();
    }

    // guarded epilogue (rounds)
#pragma unroll
    for (int mt = 0; mt < 4; mt++) {
        long long r0 = m0 + wm + mt * 16 + grp;
        long long r1 = r0 + 8;
#pragma unroll
        for (int nt = 0; nt < 8; nt++) {
            long long c = n0 + wn + nt * 8 + 2 * tig;
#pragma unroll
            for (int e = 0; e < 4; e++) {
                long long r = (e < 2) ? r0 : r1;
                long long cc = c + (e & 1);
                if (r < Mv && cc < Nv)
                    C[r * ldc + cc] = tf32r(acc[mt][nt][e]);
            }
        }
    }
}

// ================= layernorm =================
__device__ __forceinline__ float block_sum256(float v, float* red) {
    int lane = threadIdx.x & 31, w = threadIdx.x >> 5;
#pragma unroll
    for (int o = 16; o > 0; o >>= 1) v += __shfl_xor_sync(0xffffffffu, v, o);
    if (lane == 0) red[w] = v;
    __syncthreads();
    float s = 0.f;
#pragma unroll
    for (int i = 0; i < 8; i++) s += red[i];
    __syncthreads();
    return s;
}

__global__ void lnorm_kernel(const float* __restrict__ x, float* __restrict__ g,
                             const float* __restrict__ gamma_p,
                             const float* __restrict__ delta, int skipcls)
{
    __shared__ float red[8];
    int r = blockIdx.x;
    const float* xr;
    float* gr;
    if (skipcls) {
        int b = r / NP, i = r - b * NP;
        xr = x + (long long)(b * NT + 1 + i) * D_;
        gr = g + (long long)r * D_;
    } else {
        xr = x + (long long)r * D_;
        gr = g + (long long)r * D_;
    }
    int t = threadIdx.x; // 256
    float v0 = xr[t], v1 = xr[t + 256], v2 = xr[t + 512];
    float mean = block_sum256(v0 + v1 + v2, red) * (1.f / 768.f);
    float c0 = v0 - mean, c1 = v1 - mean, c2 = v2 - mean;
    float var = block_sum256(c0*c0 + c1*c1 + c2*c2, red) * (1.f / 768.f);
    float rinv = rsqrtf(var + EPS_);
    float gm = gamma_p[0];
    gr[t]       = tf32r(gm * c0 * rinv + delta[t]);
    gr[t + 256] = tf32r(gm * c1 * rinv + delta[t + 256]);
    gr[t + 512] = tf32r(gm * c2 * rinv + delta[t + 512]);
}

// ================= softmax (padded P, rounds output) =================
__global__ void softmax_kernel(float* __restrict__ P)
{
    __shared__ float red[4];
    int blk = blockIdx.x;
    int z = blk / NT, r = blk - z * NT;
    float* p = P + (long long)z * PSTR + (long long)r * KP;
    int t = threadIdx.x;          // 128
    int lane = t & 31, w = t >> 5;
    float a0 = (t < NT)       ? p[t]       : -1e30f;
    float a1 = (t + 128 < NT) ? p[t + 128] : -1e30f;
    float mx = fmaxf(a0, a1);
#pragma unroll
    for (int o = 16; o > 0; o >>= 1) mx = fmaxf(mx, __shfl_xor_sync(0xffffffffu, mx, o));
    if (lane == 0) red[w] = mx;
    __syncthreads();
    mx = fmaxf(fmaxf(red[0], red[1]), fmaxf(red[2], red[3]));
    __syncthreads();
    float e0 = (t < NT)       ? expf(BETA_ * (a0 - mx)) : 0.f;
    float e1 = (t + 128 < NT) ? expf(BETA_ * (a1 - mx)) : 0.f;
    float s = e0 + e1;
#pragma unroll
    for (int o = 16; o > 0; o >>= 1) s += __shfl_xor_sync(0xffffffffu, s, o);
    if (lane == 0) red[w] = s;
    __syncthreads();
    s = red[0] + red[1] + red[2] + red[3];
    float inv = 1.f / s;
    if (t < NT)       p[t]       = tf32r(e0 * inv);
    if (t + 128 < NT) p[t + 128] = tf32r(e1 * inv);
}

// ================= P transpose (zero-fills k>=197) =================
__global__ void transpose_p_kernel(const float* __restrict__ P, float* __restrict__ PT)
{
    __shared__ float t[32][33];
    int z = blockIdx.z;
    int k0 = blockIdx.y * 32, m0 = blockIdx.x * 32;
    const float* p = P + (long long)z * PSTR;
    float* q = PT + (long long)z * PSTR;
    int tx = threadIdx.x & 31, ty = threadIdx.x >> 5;  // 256 threads = 32x8
#pragma unroll
    for (int i = 0; i < 32; i += 8)
        t[ty + i][tx] = p[(long long)(k0 + ty + i) * KP + m0 + tx];
    __syncthreads();
#pragma unroll
    for (int i = 0; i < 32; i += 8) {
        int m = m0 + ty + i, k = k0 + tx;
        q[(long long)m * KP + k] = (k < NT) ? t[tx][ty + i] : 0.f;
    }
}

// ================= weight prep =================
__global__ void build_wqk_kernel(const float* __restrict__ Wq, const float* __restrict__ Wk,
                                 float* __restrict__ W2, float* __restrict__ WT)
{
    int idx = blockIdx.x * 256 + threadIdx.x;
    if (idx >= 2 * D_ * D_) return;
    int which = idx >= D_ * D_;
    int r = idx - which * D_ * D_;
    int h = r / (D_ * Y_);
    int rem = r - h * (D_ * Y_);
    int d = rem / Y_;
    int y = rem - d * Y_;
    float v = tf32r(which ? Wk[r] : Wq[r]);
    int hy = h * Y_ + y + which * D_;
    W2[d * QKW + hy] = v;
    WT[(long long)hy * D_ + d] = v;
}

__global__ void build_xi_kernel(const float* __restrict__ Xi,
                                float* __restrict__ XiR, float* __restrict__ XiT)
{
    __shared__ float t[32][33];
    int d0 = blockIdx.y * 32, m0 = blockIdx.x * 32;
    int tx = threadIdx.x & 31, ty = threadIdx.x >> 5;  // 256 threads
#pragma unroll
    for (int i = 0; i < 32; i += 8) {
        float v = tf32r(Xi[(long long)(d0 + ty + i) * M_ + m0 + tx]);
        XiR[(long long)(d0 + ty + i) * M_ + m0 + tx] = v;
        t[ty + i][tx] = v;
    }
    __syncthreads();
#pragma unroll
    for (int i = 0; i < 32; i += 8)
        XiT[(long long)(m0 + ty + i) * D_ + d0 + tx] = t[tx][ty + i];
}

// transpose + round a 768x768 matrix: out[j][i] = tf32r(in[i][j])
__global__ void build_wt_kernel(const float* __restrict__ W, float* __restrict__ WT)
{
    __shared__ float t[32][33];
    int i0 = blockIdx.y * 32, j0 = blockIdx.x * 32;
    int tx = threadIdx.x & 31, ty = threadIdx.x >> 5;
#pragma unroll
    for (int i = 0; i < 32; i += 8)
        t[ty + i][tx] = tf32r(W[(long long)(i0 + ty + i) * D_ + j0 + tx]);
    __syncthreads();
#pragma unroll
    for (int i = 0; i < 32; i += 8)
        WT[(long long)(j0 + ty + i) * D_ + i0 + tx] = t[tx][ty + i];
}

// ================= misc =================
__global__ void patchify_kernel(const float* __restrict__ img, float* __restrict__ out)
{
    int idx = blockIdx.x * 256 + threadIdx.x;
    if (idx >= B_ * NP * D_) return;
    int e = idx % D_;
    int rest = idx / D_;
    int p = rest % NP;
    int b = rest / NP;
    int c = e >> 8;
    int r = (e >> 4) & 15;
    int col = e & 15;
    int kh = p / 14, kw = p - kh * 14;
    out[idx] = tf32r(img[((long long)(b * 3 + c) * 224 + kh * 16 + r) * 224 + kw * 16 + col]);
}

__global__ void unpatchify_kernel(const float* __restrict__ dec, float* __restrict__ out)
{
    int idx = blockIdx.x * 256 + threadIdx.x;
    if (idx >= B_ * 3 * 224 * 224) return;
    int w = idx % 224;
    int rest = idx / 224;
    int h = rest % 224;
    rest /= 224;
    int c = rest % 3;
    int b = rest / 3;
    int kh = h >> 4, r = h & 15, kw = w >> 4, col = w & 15;
    out[idx] = dec[(long long)(b * NP + kh * 14 + kw) * D_ + c * 256 + r * 16 + col];
}

__global__ void build_x_kernel(const float* __restrict__ tok, const int* __restrict__ mask,
                               const float* __restrict__ cls, const float* __restrict__ mtok,
                               const float* __restrict__ pos, float* __restrict__ x)
{
    __shared__ int sm[NP];
    __shared__ unsigned char flag[NP];
    __shared__ int count_s;
    int b = blockIdx.x;
    int t = threadIdx.x; // 256
    if (t < NP) sm[t] = mask[b * NP + t];
    __syncthreads();
    if (t < NP) {
        int pref = 0;
        for (int j = 0; j < t; j++) pref += (sm[j] == 1);
        flag[t] = (sm[t] == 1 && pref < NMASK_) ? 1 : 0;
        if (t == NP - 1) count_s = pref + (sm[t] == 1);
    }
    __syncthreads();
    if (t == 0 && count_s < NMASK_) flag[0] = 1; // fill_value=0 padding hits token 0
    __syncthreads();
    for (int tk = 0; tk < NT; tk++) {
        const float* src;
        if (tk == 0) src = cls;
        else if (flag[tk - 1]) src = mtok;
        else src = tok + (long long)(b * NP + tk - 1) * D_;
        float* dst = x + (long long)(b * NT + tk) * D_;
        const float* pr = pos + (long long)tk * D_;
        for (int d = t; d < D_; d += 256) dst[d] = src[d] + pr[d];
    }
}

// ================= host wrappers =================
template<int EPI, bool GUARD>
static void launch_bt(const float* A, const float* B, float* C, const float* bias,
                      int Mtiles, int Ntiles, int batch, int K,
                      int lda, int ldb, int ldc,
                      long long oA0, long long oA1, long long oB0, long long oB1,
                      long long oC0, long long oC1, int innerB,
                      int Mv, int Nv, int Nz, float alpha)
{
    int smem = 4 * 128 * 36 * 4;   // 73728
    cudaFuncSetAttribute(tbt_kernel<EPI, GUARD>,
                         cudaFuncAttributeMaxDynamicSharedMemorySize, smem);
    dim3 g(Ntiles, Mtiles, batch);
    tbt_kernel<EPI, GUARD><<<g, 128, smem>>>(A, B, C, bias, K, lda, ldb, ldc,
        oA0, oA1, oB0, oB1, oC0, oC1, innerB, Mv, Nv, Nz, alpha);
}

static void launch_bn(const float* A, const float* B, float* C,
                      int Mtiles, int Ntiles, int batch, int K,
                      int lda, int ldb, int ldc,
                      long long oA0, long long oA1, long long oB0, long long oB1,
                      long long oC0, long long oC1, int innerB,
                      int Mv, int Nv)
{
    int smem = 2 * (128 * 36 + 32 * 136) * 4;
    cudaFuncSetAttribute(tbn_kernel<EPI_STORE_T>,
                         cudaFuncAttributeMaxDynamicSharedMemorySize, smem);
    dim3 g(Ntiles, Mtiles, batch);
    tbn_kernel<EPI_STORE_T><<<g, 128, smem>>>(A, B, C, K, lda, ldb, ldc,
        oA0, oA1, oB0, oB1, oC0, oC1, innerB, Mv, Nv, 0.f);
}

extern "C" void kernel_launch(void* const* d_in, const int* in_sizes, int n_in,
                              void* d_out, int out_size)
{
    const float* img   = (const float*)d_in[0];
    const int*   mask  = (const int*)  d_in[1];
    const float* enc_W = (const float*)d_in[2];
    const float* enc_b = (const float*)d_in[3];
    const float* dec_W = (const float*)d_in[4];
    const float* dec_b = (const float*)d_in[5];
    const float* cls   = (const float*)d_in[6];
    const float* mtok  = (const float*)d_in[7];
    const float* pos   = (const float*)d_in[8];
    const float* Wq    = (const float*)d_in[9];
    const float* Wk    = (const float*)d_in[10];
    const float* Xi    = (const float*)d_in[11];
    const float* gamma = (const float*)d_in[12];
    const float* delta = (const float*)d_in[13];
    float* out = (float*)d_out;

    float *ppat, *ptok, *px, *pg, *pqk, *poqk, *pP, *pPT, *pZ;
    float *pW2, *pWT, *pXiR, *pXiT, *pencT, *pdecT, *pdec;
    cudaGetSymbolAddress((void**)&ppat, d_patches);
    cudaGetSymbolAddress((void**)&ptok, d_tok);
    cudaGetSymbolAddress((void**)&px,   d_x);
    cudaGetSymbolAddress((void**)&pg,   d_g);
    cudaGetSymbolAddress((void**)&pqk,  d_qk);
    cudaGetSymbolAddress((void**)&poqk, d_oqk);
    cudaGetSymbolAddress((void**)&pP,   d_P);
    cudaGetSymbolAddress((void**)&pPT,  d_PT);
    cudaGetSymbolAddress((void**)&pZ,   d_Z);
    cudaGetSymbolAddress((void**)&pW2,  d_W2);
    cudaGetSymbolAddress((void**)&pWT,  d_WT);
    cudaGetSymbolAddress((void**)&pXiR, d_XiR);
    cudaGetSymbolAddress((void**)&pXiT, d_XiT);
    cudaGetSymbolAddress((void**)&pencT, d_encT);
    cudaGetSymbolAddress((void**)&pdecT, d_decT);
    cudaGetSymbolAddress((void**)&pdec, d_dec);

    const int ROWS  = B_ * NT;   // 3152
    const int ROWSE = B_ * NP;   // 3136
    const long long GB2 = (long long)NT * QKW;   // per-batch token block in qk/oqk

    // weight prep
    build_wqk_kernel<<<(2 * D_ * D_ + 255) / 256, 256>>>(Wq, Wk, pW2, pWT);
    build_xi_kernel<<<dim3(M_ / 32, D_ / 32), 256>>>(Xi, pXiR, pXiT);
    build_wt_kernel<<<dim3(24, 24), 256>>>(enc_W, pencT);
    build_wt_kernel<<<dim3(24, 24), 256>>>(dec_W, pdecT);

    // encode (tensor, guarded, +bias)
    patchify_kernel<<<(B_ * NP * D_ + 255) / 256, 256>>>(img, ppat);
    launch_bt<EPI_BIAS, true>(ppat, pencT, ptok, enc_b,
        25, 6, 1, D_, D_, D_, D_, 0,0,0,0,0,0, 1, ROWSE, D_, D_, 0.f);
    build_x_kernel<<<B_, 256>>>(ptok, mask, cls, mtok, pos, px);

    for (int s = 0; s < NSTEPS_; s++) {
        lnorm_kernel<<<ROWS, 256>>>(px, pg, gamma, delta, 0);
        // q|k = g @ WT^T
        launch_bt<EPI_STORE_T, false>(pg, pWT, pqk, 0,
            25, 12, 1, D_, D_, D_, QKW, 0,0,0,0,0,0, 1, 0,0,0, 0.f);
        // S = q @ k^T (guarded, zero-pads cols [197,224))
        launch_bt<EPI_STORE, true>(pqk, pqk + 768, pP, 0,
            2, 2, NBH, Y_, QKW, QKW, KP,
            GB2, 64, GB2, 64, (long long)HEADS_ * PSTR, PSTR, HEADS_,
            NT, NT, KP, 0.f);
        softmax_kernel<<<NBH * NT, 128>>>(pP);
        transpose_p_kernel<<<dim3(KP / 32, KP / 32, NBH), 256>>>(pP, pPT);
        // oq = P @ k (BN)
        launch_bn(pP, pqk + 768, poqk,
            2, 1, NBH, KP, KP, QKW, QKW,
            (long long)HEADS_ * PSTR, PSTR, GB2, 64, GB2, 64, HEADS_,
            NT, Y_);
        // ok = P^T @ q (BN)
        launch_bn(pPT, pqk, poqk + 768,
            2, 1, NBH, KP, KP, QKW, QKW,
            (long long)HEADS_ * PSTR, PSTR, GB2, 64, GB2, 64, HEADS_,
            NT, Y_);
        // x += alpha * [oq|ok] @ W2  (BT: B = W2 [d][hy])
        launch_bt<EPI_AXPY, false>(poqk, pW2, px, 0,
            25, 6, 1, QKW, QKW, QKW, D_, 0,0,0,0,0,0, 1, 0,0,0, ALPHA_);
        // Z = relu(g @ Xi)  (BT: B = XiT [mu][d])
        launch_bt<EPI_RELU_T, false>(pg, pXiT, pZ, 0,
            25, 24, 1, D_, D_, D_, M_, 0,0,0,0,0,0, 1, 0,0,0, 0.f);
        // x += alpha * Z @ Xi^T  (BT: B = XiR [d][mu])
        launch_bt<EPI_AXPY, false>(pZ, pXiR, px, 0,
            25, 6, 1, M_, M_, M_, D_, 0,0,0,0,0,0, 1, 0,0,0, ALPHA_);
    }

    // decode (tensor, guarded, +bias)
    lnorm_kernel<<<ROWSE, 256>>>(px, pg, gamma, delta, 1);
    launch_bt<EPI_BIAS, true>(pg, pdecT, pdec, dec_b,
        25, 6, 1, D_, D_, D_, D_, 0,0,0,0,0,0, 1, ROWSE, D_, D_, 0.f);
    unpatchify_kernel<<<(B_ * 3 * 224 * 224 + 255) / 256, 256>>>(pdec, out);
}

// round 6
// speedup vs baseline: 4.6354x; 1.7268x over previous
#include <cuda_runtime.h>
#include <cuda_fp16.h>
#include <cstdint>

#define B_      16
#define NP      196
#define NT      197
#define D_      768
#define M_      3072
#define HEADS_  12
#define Y_      64
#define NSTEPS_ 12
#define ALPHA_  0.1f
#define BETA_   0.125f
#define EPS_    1e-5f
#define NMASK_  100
#define RP      3200              // padded row count (25 * 128)
#define QKW     1536              // fused q|k width
#define KP      224               // padded token dim for P (7*32)
#define PSTR    (256*KP)          // per-(b,h) P slice stride
#define NBH     (B_*HEADS_)      // 192

// ---------------- scratch (device globals; zero-initialized) ----------------
__device__ __half d_patches[RP*D_];
__device__ float  d_tok[B_*NP*D_];
__device__ float  d_x[RP*D_];
__device__ __half d_g[RP*D_];
__device__ __half d_qk[(RP+64)*QKW];
__device__ __half d_oqk[RP*QKW];
__device__ float  d_S[NBH*PSTR];
__device__ __half d_Ph[NBH*PSTR];
__device__ __half d_PTh[NBH*PSTR];
__device__ __half d_Z[RP*M_];
__device__ __half d_W2h[D_*QKW];   // [d][hy|768+hy]   B for backproj (BT)
__device__ __half d_WTh[QKW*D_];   // [hy][d]          B for projection (BT)
__device__ __half d_XiRh[D_*M_];   // Xi               B for hopfield bwd (BT)
__device__ __half d_XiTh[M_*D_];   // Xi^T             B for hopfield fwd (BT)
__device__ __half d_encTh[D_*D_];  // enc_W^T
__device__ __half d_decTh[D_*D_];  // dec_W^T
__device__ float  d_dec[B_*NP*D_];

#define EPI_STORE_S 0   // float out, guarded, zero-pads cols [Nv,Nz)
#define EPI_BIAS    1   // float out + bias, guarded rows
#define EPI_RELU_H  2   // half out, relu
#define EPI_AXPY    3   // float out, C += alpha*acc
#define EPI_STORE_H 4   // half out

__device__ __forceinline__ uint32_t smem_u32(const void* p) {
    uint32_t a;
    asm("{ .reg .u64 t; cvta.to.shared.u64 t, %1; cvt.u32.u64 %0, t; }" : "=r"(a) : "l"(p));
    return a;
}
__device__ __forceinline__ void ldsm4(uint32_t* r, uint32_t addr) {
    asm volatile("ldmatrix.sync.aligned.m8n8.x4.shared.b16 {%0,%1,%2,%3}, [%4];"
        : "=r"(r[0]), "=r"(r[1]), "=r"(r[2]), "=r"(r[3]) : "r"(addr));
}
__device__ __forceinline__ void ldsm4t(uint32_t* r, uint32_t addr) {
    asm volatile("ldmatrix.sync.aligned.m8n8.x4.trans.shared.b16 {%0,%1,%2,%3}, [%4];"
        : "=r"(r[0]), "=r"(r[1]), "=r"(r[2]), "=r"(r[3]) : "r"(addr));
}
#define MMA16(acc, a, b0, b1) \
    asm("mma.sync.aligned.m16n8k16.row.col.f32.f16.f16.f32 " \
        "{%0,%1,%2,%3}, {%4,%5,%6,%7}, {%8,%9}, {%0,%1,%2,%3};" \
        : "+f"((acc)[0]), "+f"((acc)[1]), "+f"((acc)[2]), "+f"((acc)[3]) \
        : "r"((a)[0]), "r"((a)[1]), "r"((a)[2]), "r"((a)[3]), "r"(b0), "r"(b1))

// ---- tile loaders (cp.async, 16B chunks) ----
// k-major tile: 128 rows x 32 halves, smem stride 40 halves (80B)
__device__ __forceinline__ void ldA16(__half* s, const __half* gp, int ld, int tid) {
    const __half* grow = gp + (long long)tid * ld;
    uint32_t srow = smem_u32(s + tid * 40);
#pragma unroll
    for (int i = 0; i < 4; i++)
        asm volatile("cp.async.cg.shared.global [%0], [%1], 16;"
                     :: "r"(srow + i * 16), "l"(grow + i * 8));
}
// BN tile: 32 k-rows x 128 n-halves, smem stride 136 halves (272B)
__device__ __forceinline__ void ldB16n(__half* s, const __half* gp, int ld, int tid) {
    int row = tid >> 2;
    int c0 = (tid & 3) * 32;
    const __half* grow = gp + (long long)row * ld + c0;
    uint32_t srow = smem_u32(s + row * 136 + c0);
#pragma unroll
    for (int i = 0; i < 4; i++)
        asm volatile("cp.async.cg.shared.global [%0], [%1], 16;"
                     :: "r"(srow + i * 16), "l"(grow + i * 8));
}

// ================= BT fp16 mma GEMM =================
// C[m,n] (op)= sum_k A[m,k]*B[n,k]; A:[M x K] lda, B:[N x K] ldb (halves, k-major).
// Block 128x128, K-chunk 32, 2-stage cp.async, 4 warps of 64x64.
template<int EPI, bool GUARD>
__global__ __launch_bounds__(128, 2) void hbt_kernel(
    const __half* __restrict__ A, const __half* __restrict__ Bm,
    void* __restrict__ Cv, const float* __restrict__ bias,
    int K, int lda, int ldb, int ldc,
    long long oA0, long long oA1, long long oB0, long long oB1,
    long long oC0, long long oC1, int innerB,
    int Mv, int Nv, int Nz, float alpha)
{
    extern __shared__ __half sh[];
    constexpr int TSZ = 128 * 40;
    __half* sA[2] = { sh,           sh + 2 * TSZ };
    __half* sB[2] = { sh + TSZ,     sh + 3 * TSZ };

    int z = blockIdx.z;
    int zo = z / innerB, zi = z - zo * innerB;
    A  += zo * oA0 + zi * oA1;
    Bm += zo * oB0 + zi * oB1;

    const int tid = threadIdx.x;
    const int lane = tid & 31, wid = tid >> 5;
    const int grp = lane >> 2, tig = lane & 3;
    const int wm = (wid >> 1) * 64, wn = (wid & 1) * 64;
    const long long m0 = (long long)blockIdx.y * 128;
    const long long n0 = (long long)blockIdx.x * 128;
    A += m0 * lda;
    Bm += n0 * ldb;

    const uint32_t laneoff = (lane & 15) * 80 + (lane >> 4) * 16;

    float acc[4][8][4];
#pragma unroll
    for (int i = 0; i < 4; i++)
#pragma unroll
        for (int j = 0; j < 8; j++)
#pragma unroll
            for (int c = 0; c < 4; c++) acc[i][j][c] = 0.f;

    const int nk = K >> 5;
    ldA16(sA[0], A, lda, tid);
    ldA16(sB[0], Bm, ldb, tid);
    asm volatile("cp.async.commit_group;" ::: "memory");

    for (int kt = 0; kt < nk; kt++) {
        if (kt + 1 < nk) {
            int st = (kt + 1) & 1;
            ldA16(sA[st], A + (kt + 1) * 32, lda, tid);
            ldA16(sB[st], Bm + (kt + 1) * 32, ldb, tid);
            asm volatile("cp.async.commit_group;" ::: "memory");
            asm volatile("cp.async.wait_group 1;" ::: "memory");
        } else {
            asm volatile("cp.async.wait_group 0;" ::: "memory");
        }
        __syncthreads();

        const uint32_t aBase = smem_u32(sA[kt & 1]) + wm * 80 + laneoff;
        const uint32_t bBase = smem_u32(sB[kt & 1]) + wn * 80 + laneoff;
#pragma unroll
        for (int kk = 0; kk < 32; kk += 16) {
            uint32_t af[4][4], bp[4][4];
#pragma unroll
            for (int mt = 0; mt < 4; mt++)
                ldsm4(af[mt], aBase + mt * 16 * 80 + kk * 2);
#pragma unroll
            for (int nb = 0; nb < 4; nb++)
                ldsm4(bp[nb], bBase + nb * 16 * 80 + kk * 2);
#pragma unroll
            for (int mt = 0; mt < 4; mt++)
#pragma unroll
                for (int nt = 0; nt < 8; nt++)
                    MMA16(acc[mt][nt], af[mt],
                          bp[nt >> 1][nt & 1], bp[nt >> 1][2 + (nt & 1)]);
        }
        __syncthreads();
    }

    float* Cf = (float*)Cv;
    __half* Ch = (__half*)Cv;
    if (GUARD) {
        Cf += zo * oC0 + zi * oC1;
        Ch += zo * oC0 + zi * oC1;
#pragma unroll
        for (int mt = 0; mt < 4; mt++) {
            long long r0 = m0 + wm + mt * 16 + grp;
#pragma unroll
            for (int nt = 0; nt < 8; nt++) {
                long long c = n0 + wn + nt * 8 + 2 * tig;
#pragma unroll
                for (int e = 0; e < 4; e++) {
                    long long r = r0 + (e >> 1) * 8;
                    long long cc = c + (e & 1);
                    float v = acc[mt][nt][e];
                    if (r < Mv) {
                        if (cc < Nv) {
                            if (EPI == EPI_STORE_S) Cf[r * ldc + cc] = v;
                            if (EPI == EPI_BIAS)    Cf[r * ldc + cc] = v + bias[cc];
                            if (EPI == EPI_STORE_H) Ch[r * ldc + cc] = __float2half(v);
                        } else if (cc < Nz) {
                            if (EPI == EPI_STORE_S) Cf[r * ldc + cc] = 0.f;
                        }
                    }
                }
            }
        }
    } else {
#pragma unroll
        for (int mt = 0; mt < 4; mt++) {
            long long r0 = m0 + wm + mt * 16 + grp;
#pragma unroll
            for (int nt = 0; nt < 8; nt++) {
                int col = nt * 8 + 2 * tig;
                float2 v0 = make_float2(acc[mt][nt][0], acc[mt][nt][1]);
                float2 v1 = make_float2(acc[mt][nt][2], acc[mt][nt][3]);
                if (EPI == EPI_AXPY) {
                    float* c0 = Cf + r0 * ldc + n0 + wn + col;
                    float* c1 = c0 + 8LL * ldc;
                    float2 o0 = *(float2*)c0;
                    float2 o1 = *(float2*)c1;
                    o0.x += alpha * v0.x; o0.y += alpha * v0.y;
                    o1.x += alpha * v1.x; o1.y += alpha * v1.y;
                    *(float2*)c0 = o0;
                    *(float2*)c1 = o1;
                } else {
                    __half* c0 = Ch + r0 * ldc + n0 + wn + col;
                    __half* c1 = c0 + 8LL * ldc;
                    if (EPI == EPI_RELU_H) {
                        v0.x = fmaxf(v0.x, 0.f); v0.y = fmaxf(v0.y, 0.f);
                        v1.x = fmaxf(v1.x, 0.f); v1.y = fmaxf(v1.y, 0.f);
                    }
                    *(__half2*)c0 = __floats2half2_rn(v0.x, v0.y);
                    *(__half2*)c1 = __floats2half2_rn(v1.x, v1.y);
                }
            }
        }
    }
}

// ================= BN fp16 mma GEMM (oq/ok: B row-major [K x N]) =================
__global__ __launch_bounds__(128, 2) void hbn_kernel(
    const __half* __restrict__ A, const __half* __restrict__ Bm,
    __half* __restrict__ C, int K, int lda, int ldb, int ldc,
    long long oA0, long long oA1, long long oB0, long long oB1,
    long long oC0, long long oC1, int innerB,
    int Mv, int Nv)
{
    extern __shared__ __half sh[];
    constexpr int ASZ = 128 * 40;
    constexpr int BSZ = 32 * 136;
    __half* sA[2] = { sh, sh + ASZ + BSZ };
    __half* sB[2] = { sh + ASZ, sh + 2 * ASZ + BSZ };

    int z = blockIdx.z;
    int zo = z / innerB, zi = z - zo * innerB;
    A  += zo * oA0 + zi * oA1;
    Bm += zo * oB0 + zi * oB1;
    C  += zo * oC0 + zi * oC1;

    const int tid = threadIdx.x;
    const int lane = tid & 31, wid = tid >> 5;
    const int grp = lane >> 2, tig = lane & 3;
    const int wm = (wid >> 1) * 64, wn = (wid & 1) * 64;
    const long long m0 = (long long)blockIdx.y * 128;
    A += m0 * lda;

    const uint32_t laneoffA = (lane & 15) * 80 + (lane >> 4) * 16;
    const uint32_t laneoffB = (lane & 15) * 272 + (lane >> 4) * 16;

    float acc[4][8][4];
#pragma unroll
    for (int i = 0; i < 4; i++)
#pragma unroll
        for (int j = 0; j < 8; j++)
#pragma unroll
            for (int c = 0; c < 4; c++) acc[i][j][c] = 0.f;

    const int nk = K >> 5;
    ldA16(sA[0], A, lda, tid);
    ldB16n(sB[0], Bm, ldb, tid);
    asm volatile("cp.async.commit_group;" ::: "memory");

    for (int kt = 0; kt < nk; kt++) {
        if (kt + 1 < nk) {
            int st = (kt + 1) & 1;
            ldA16(sA[st], A + (kt + 1) * 32, lda, tid);
            ldB16n(sB[st], Bm + (long long)(kt + 1) * 32 * ldb, ldb, tid);
            asm volatile("cp.async.commit_group;" ::: "memory");
            asm volatile("cp.async.wait_group 1;" ::: "memory");
        } else {
            asm volatile("cp.async.wait_group 0;" ::: "memory");
        }
        __syncthreads();

        const uint32_t aBase = smem_u32(sA[kt & 1]) + wm * 80 + laneoffA;
        const uint32_t bBase = smem_u32(sB[kt & 1]) + wn * 2 + laneoffB;
#pragma unroll
        for (int kk = 0; kk < 32; kk += 16) {
            uint32_t af[4][4], bp[4][4];
#pragma unroll
            for (int mt = 0; mt < 4; mt++)
                ldsm4(af[mt], aBase + mt * 16 * 80 + kk * 2);
#pragma unroll
            for (int nb = 0; nb < 4; nb++)
                ldsm4t(bp[nb], bBase + kk * 272 + nb * 32);
#pragma unroll
            for (int mt = 0; mt < 4; mt++)
#pragma unroll
                for (int nt = 0; nt < 8; nt++)
                    MMA16(acc[mt][nt], af[mt],
                          bp[nt >> 1][(nt & 1) * 2], bp[nt >> 1][(nt & 1) * 2 + 1]);
        }
        __syncthreads();
    }

    // guarded half store
#pragma unroll
    for (int mt = 0; mt < 4; mt++) {
        long long r0 = m0 + wm + mt * 16 + grp;
#pragma unroll
        for (int nt = 0; nt < 8; nt++) {
            long long c = wn + nt * 8 + 2 * tig;
#pragma unroll
            for (int e = 0; e < 4; e++) {
                long long r = r0 + (e >> 1) * 8;
                long long cc = c + (e & 1);
                if (r < Mv && cc < Nv)
                    C[r * ldc + cc] = __float2half(acc[mt][nt][e]);
            }
        }
    }
}

// ================= layernorm (fp32 in, half out) =================
__device__ __forceinline__ float block_sum256(float v, float* red) {
    int lane = threadIdx.x & 31, w = threadIdx.x >> 5;
#pragma unroll
    for (int o = 16; o > 0; o >>= 1) v += __shfl_xor_sync(0xffffffffu, v, o);
    if (lane == 0) red[w] = v;
    __syncthreads();
    float s = 0.f;
#pragma unroll
    for (int i = 0; i < 8; i++) s += red[i];
    __syncthreads();
    return s;
}

__global__ void lnorm_kernel(const float* __restrict__ x, __half* __restrict__ g,
                             const float* __restrict__ gamma_p,
                             const float* __restrict__ delta, int skipcls)
{
    __shared__ float red[8];
    int r = blockIdx.x;
    const float* xr;
    __half* gr;
    if (skipcls) {
        int b = r / NP, i = r - b * NP;
        xr = x + (long long)(b * NT + 1 + i) * D_;
        gr = g + (long long)r * D_;
    } else {
        xr = x + (long long)r * D_;
        gr = g + (long long)r * D_;
    }
    int t = threadIdx.x; // 256
    float v0 = xr[t], v1 = xr[t + 256], v2 = xr[t + 512];
    float mean = block_sum256(v0 + v1 + v2, red) * (1.f / 768.f);
    float c0 = v0 - mean, c1 = v1 - mean, c2 = v2 - mean;
    float var = block_sum256(c0*c0 + c1*c1 + c2*c2, red) * (1.f / 768.f);
    float rinv = rsqrtf(var + EPS_);
    float gm = gamma_p[0];
    gr[t]       = __float2half(gm * c0 * rinv + delta[t]);
    gr[t + 256] = __float2half(gm * c1 * rinv + delta[t + 256]);
    gr[t + 512] = __float2half(gm * c2 * rinv + delta[t + 512]);
}

// ================= softmax (fp32 S in, half P out) =================
__global__ void softmax_kernel(const float* __restrict__ S, __half* __restrict__ Ph)
{
    __shared__ float red[4];
    int blk = blockIdx.x;
    int z = blk / NT, r = blk - z * NT;
    const float* p = S + (long long)z * PSTR + (long long)r * KP;
    __half* q = Ph + (long long)z * PSTR + (long long)r * KP;
    int t = threadIdx.x;          // 128
    int lane = t & 31, w = t >> 5;
    float a0 = (t < NT)       ? p[t]       : -1e30f;
    float a1 = (t + 128 < NT) ? p[t + 128] : -1e30f;
    float mx = fmaxf(a0, a1);
#pragma unroll
    for (int o = 16; o > 0; o >>= 1) mx = fmaxf(mx, __shfl_xor_sync(0xffffffffu, mx, o));
    if (lane == 0) red[w] = mx;
    __syncthreads();
    mx = fmaxf(fmaxf(red[0], red[1]), fmaxf(red[2], red[3]));
    __syncthreads();
    float e0 = (t < NT)       ? expf(BETA_ * (a0 - mx)) : 0.f;
    float e1 = (t + 128 < NT) ? expf(BETA_ * (a1 - mx)) : 0.f;
    float s = e0 + e1;
#pragma unroll
    for (int o = 16; o > 0; o >>= 1) s += __shfl_xor_sync(0xffffffffu, s, o);
    if (lane == 0) red[w] = s;
    __syncthreads();
    s = red[0] + red[1] + red[2] + red[3];
    float inv = 1.f / s;
    if (t < NT)       q[t]       = __float2half(e0 * inv);
    if (t + 128 < NT) q[t + 128] = __float2half(e1 * inv);
}

// ================= P transpose (half, zero-fills k>=197) =================
__global__ void transpose_p_kernel(const __half* __restrict__ P, __half* __restrict__ PT)
{
    __shared__ __half t[32][33];
    int z = blockIdx.z;
    int k0 = blockIdx.y * 32, m0 = blockIdx.x * 32;
    const __half* p = P + (long long)z * PSTR;
    __half* q = PT + (long long)z * PSTR;
    int tx = threadIdx.x & 31, ty = threadIdx.x >> 5;  // 256 threads = 32x8
#pragma unroll
    for (int i = 0; i < 32; i += 8)
        t[ty + i][tx] = p[(long long)(k0 + ty + i) * KP + m0 + tx];
    __syncthreads();
#pragma unroll
    for (int i = 0; i < 32; i += 8) {
        int m = m0 + ty + i, k = k0 + tx;
        q[(long long)m * KP + k] = (k < NT) ? t[tx][ty + i] : __half(0.f);
    }
}

// ================= weight prep =================
__global__ void build_wqk_kernel(const float* __restrict__ Wq, const float* __restrict__ Wk,
                                 __half* __restrict__ W2, __half* __restrict__ WT)
{
    int idx = blockIdx.x * 256 + threadIdx.x;
    if (idx >= 2 * D_ * D_) return;
    int which = idx >= D_ * D_;
    int r = idx - which * D_ * D_;
    int h = r / (D_ * Y_);
    int rem = r - h * (D_ * Y_);
    int d = rem / Y_;
    int y = rem - d * Y_;
    __half v = __float2half(which ? Wk[r] : Wq[r]);
    int hy = h * Y_ + y + which * D_;
    W2[d * QKW + hy] = v;
    WT[(long long)hy * D_ + d] = v;
}

__global__ void build_xi_kernel(const float* __restrict__ Xi,
                                __half* __restrict__ XiR, __half* __restrict__ XiT)
{
    __shared__ __half t[32][33];
    int d0 = blockIdx.y * 32, m0 = blockIdx.x * 32;
    int tx = threadIdx.x & 31, ty = threadIdx.x >> 5;  // 256 threads
#pragma unroll
    for (int i = 0; i < 32; i += 8) {
        __half v = __float2half(Xi[(long long)(d0 + ty + i) * M_ + m0 + tx]);
        XiR[(long long)(d0 + ty + i) * M_ + m0 + tx] = v;
        t[ty + i][tx] = v;
    }
    __syncthreads();
#pragma unroll
    for (int i = 0; i < 32; i += 8)
        XiT[(long long)(m0 + ty + i) * D_ + d0 + tx] = t[tx][ty + i];
}

__global__ void build_wt_kernel(const float* __restrict__ W, __half* __restrict__ WT)
{
    __shared__ __half t[32][33];
    int i0 = blockIdx.y * 32, j0 = blockIdx.x * 32;
    int tx = threadIdx.x & 31, ty = threadIdx.x >> 5;
#pragma unroll
    for (int i = 0; i < 32; i += 8)
        t[ty + i][tx] = __float2half(W[(long long)(i0 + ty + i) * D_ + j0 + tx]);
    __syncthreads();
#pragma unroll
    for (int i = 0; i < 32; i += 8)
        WT[(long long)(j0 + ty + i) * D_ + i0 + tx] = t[tx][ty + i];
}

// ================= misc =================
__global__ void patchify_kernel(const float* __restrict__ img, __half* __restrict__ out)
{
    int idx = blockIdx.x * 256 + threadIdx.x;
    if (idx >= B_ * NP * D_) return;
    int e = idx % D_;
    int rest = idx / D_;
    int p = rest % NP;
    int b = rest / NP;
    int c = e >> 8;
    int r = (e >> 4) & 15;
    int col = e & 15;
    int kh = p / 14, kw = p - kh * 14;
    out[idx] = __float2half(img[((long long)(b * 3 + c) * 224 + kh * 16 + r) * 224 + kw * 16 + col]);
}

__global__ void unpatchify_kernel(const float* __restrict__ dec, float* __restrict__ out)
{
    int idx = blockIdx.x * 256 + threadIdx.x;
    if (idx >= B_ * 3 * 224 * 224) return;
    int w = idx % 224;
    int rest = idx / 224;
    int h = rest % 224;
    rest /= 224;
    int c = rest % 3;
    int b = rest / 3;
    int kh = h >> 4, r = h & 15, kw = w >> 4, col = w & 15;
    out[idx] = dec[(long long)(b * NP + kh * 14 + kw) * D_ + c * 256 + r * 16 + col];
}

__global__ void build_x_kernel(const float* __restrict__ tok, const int* __restrict__ mask,
                               const float* __restrict__ cls, const float* __restrict__ mtok,
                               const float* __restrict__ pos, float* __restrict__ x)
{
    __shared__ int sm[NP];
    __shared__ unsigned char flag[NP];
    __shared__ int count_s;
    int b = blockIdx.x;
    int t = threadIdx.x; // 256
    if (t < NP) sm[t] = mask[b * NP + t];
    __syncthreads();
    if (t < NP) {
        int pref = 0;
        for (int j = 0; j < t; j++) pref += (sm[j] == 1);
        flag[t] = (sm[t] == 1 && pref < NMASK_) ? 1 : 0;
        if (t == NP - 1) count_s = pref + (sm[t] == 1);
    }
    __syncthreads();
    if (t == 0 && count_s < NMASK_) flag[0] = 1; // fill_value=0 padding hits token 0
    __syncthreads();
    for (int tk = 0; tk < NT; tk++) {
        const float* src;
        if (tk == 0) src = cls;
        else if (flag[tk - 1]) src = mtok;
        else src = tok + (long long)(b * NP + tk - 1) * D_;
        float* dst = x + (long long)(b * NT + tk) * D_;
        const float* pr = pos + (long long)tk * D_;
        for (int d = t; d < D_; d += 256) dst[d] = src[d] + pr[d];
    }
}

// ================= host wrappers =================
template<int EPI, bool GUARD>
static void launch_bt(const __half* A, const __half* B, void* C, const float* bias,
                      int Mtiles, int Ntiles, int batch, int K,
                      int lda, int ldb, int ldc,
                      long long oA0, long long oA1, long long oB0, long long oB1,
                      long long oC0, long long oC1, int innerB,
                      int Mv, int Nv, int Nz, float alpha)
{
    int smem = 4 * 128 * 40 * 2;   // 40960
    cudaFuncSetAttribute(hbt_kernel<EPI, GUARD>,
                         cudaFuncAttributeMaxDynamicSharedMemorySize, smem);
    dim3 g(Ntiles, Mtiles, batch);
    hbt_kernel<EPI, GUARD><<<g, 128, smem>>>(A, B, C, bias, K, lda, ldb, ldc,
        oA0, oA1, oB0, oB1, oC0, oC1, innerB, Mv, Nv, Nz, alpha);
}

static void launch_bn(const __half* A, const __half* B, __half* C,
                      int Mtiles, int batch, int K,
                      int lda, int ldb, int ldc,
                      long long oA0, long long oA1, long long oB0, long long oB1,
                      long long oC0, long long oC1, int innerB,
                      int Mv, int Nv)
{
    int smem = 2 * (128 * 40 + 32 * 136) * 2;   // 37888
    cudaFuncSetAttribute(hbn_kernel,
                         cudaFuncAttributeMaxDynamicSharedMemorySize, smem);
    dim3 g(1, Mtiles, batch);
    hbn_kernel<<<g, 128, smem>>>(A, B, C, K, lda, ldb, ldc,
        oA0, oA1, oB0, oB1, oC0, oC1, innerB, Mv, Nv);
}

extern "C" void kernel_launch(void* const* d_in, const int* in_sizes, int n_in,
                              void* d_out, int out_size)
{
    const float* img   = (const float*)d_in[0];
    const int*   mask  = (const int*)  d_in[1];
    const float* enc_W = (const float*)d_in[2];
    const float* enc_b = (const float*)d_in[3];
    const float* dec_W = (const float*)d_in[4];
    const float* dec_b = (const float*)d_in[5];
    const float* cls   = (const float*)d_in[6];
    const float* mtok  = (const float*)d_in[7];
    const float* pos   = (const float*)d_in[8];
    const float* Wq    = (const float*)d_in[9];
    const float* Wk    = (const float*)d_in[10];
    const float* Xi    = (const float*)d_in[11];
    const float* gamma = (const float*)d_in[12];
    const float* delta = (const float*)d_in[13];
    float* out = (float*)d_out;

    __half *ppatH, *pgH, *pqkH, *poqkH, *pPh, *pPTh, *pZH;
    __half *pW2h, *pWTh, *pXiRh, *pXiTh, *pencTh, *pdecTh;
    float *ptok, *px, *pS, *pdec;
    cudaGetSymbolAddress((void**)&ppatH, d_patches);
    cudaGetSymbolAddress((void**)&ptok,  d_tok);
    cudaGetSymbolAddress((void**)&px,    d_x);
    cudaGetSymbolAddress((void**)&pgH,   d_g);
    cudaGetSymbolAddress((void**)&pqkH,  d_qk);
    cudaGetSymbolAddress((void**)&poqkH, d_oqk);
    cudaGetSymbolAddress((void**)&pS,    d_S);
    cudaGetSymbolAddress((void**)&pPh,   d_Ph);
    cudaGetSymbolAddress((void**)&pPTh,  d_PTh);
    cudaGetSymbolAddress((void**)&pZH,   d_Z);
    cudaGetSymbolAddress((void**)&pW2h,  d_W2h);
    cudaGetSymbolAddress((void**)&pWTh,  d_WTh);
    cudaGetSymbolAddress((void**)&pXiRh, d_XiRh);
    cudaGetSymbolAddress((void**)&pXiTh, d_XiTh);
    cudaGetSymbolAddress((void**)&pencTh, d_encTh);
    cudaGetSymbolAddress((void**)&pdecTh, d_decTh);
    cudaGetSymbolAddress((void**)&pdec,  d_dec);

    const int ROWS  = B_ * NT;   // 3152
    const int ROWSE = B_ * NP;   // 3136
    const long long GB2 = (long long)NT * QKW;   // per-batch token block (halves)

    // weight prep
    build_wqk_kernel<<<(2 * D_ * D_ + 255) / 256, 256>>>(Wq, Wk, pW2h, pWTh);
    build_xi_kernel<<<dim3(M_ / 32, D_ / 32), 256>>>(Xi, pXiRh, pXiTh);
    build_wt_kernel<<<dim3(24, 24), 256>>>(enc_W, pencTh);
    build_wt_kernel<<<dim3(24, 24), 256>>>(dec_W, pdecTh);

    // encode
    patchify_kernel<<<(B_ * NP * D_ + 255) / 256, 256>>>(img, ppatH);
    launch_bt<EPI_BIAS, true>(ppatH, pencTh, ptok, enc_b,
        25, 6, 1, D_, D_, D_, D_, 0,0,0,0,0,0, 1, ROWSE, D_, D_, 0.f);
    build_x_kernel<<<B_, 256>>>(ptok, mask, cls, mtok, pos, px);

    for (int s = 0; s < NSTEPS_; s++) {
        lnorm_kernel<<<ROWS, 256>>>(px, pgH, gamma, delta, 0);
        // q|k = g @ WT^T
        launch_bt<EPI_STORE_H, false>(pgH, pWTh, pqkH, 0,
            25, 12, 1, D_, D_, D_, QKW, 0,0,0,0,0,0, 1, 0,0,0, 0.f);
        // S = q @ k^T (float out, zero-pads cols [197,224))
        launch_bt<EPI_STORE_S, true>(pqkH, pqkH + 768, pS, 0,
            2, 2, NBH, Y_, QKW, QKW, KP,
            GB2, 64, GB2, 64, (long long)HEADS_ * PSTR, PSTR, HEADS_,
            NT, NT, KP, 0.f);
        softmax_kernel<<<NBH * NT, 128>>>(pS, pPh);
        transpose_p_kernel<<<dim3(KP / 32, KP / 32, NBH), 256>>>(pPh, pPTh);
        // oq = P @ k (BN)
        launch_bn(pPh, pqkH + 768, poqkH,
            2, NBH, KP, KP, QKW, QKW,
            (long long)HEADS_ * PSTR, PSTR, GB2, 64, GB2, 64, HEADS_,
            NT, Y_);
        // ok = P^T @ q (BN)
        launch_bn(pPTh, pqkH, poqkH + 768,
            2, NBH, KP, KP, QKW, QKW,
            (long long)HEADS_ * PSTR, PSTR, GB2, 64, GB2, 64, HEADS_,
            NT, Y_);
        // x += alpha * [oq|ok] @ W2
        launch_bt<EPI_AXPY, false>(poqkH, pW2h, px, 0,
            25, 6, 1, QKW, QKW, QKW, D_, 0,0,0,0,0,0, 1, 0,0,0, ALPHA_);
        // Z = relu(g @ Xi)
        launch_bt<EPI_RELU_H, false>(pgH, pXiTh, pZH, 0,
            25, 24, 1, D_, D_, D_, M_, 0,0,0,0,0,0, 1, 0,0,0, 0.f);
        // x += alpha * Z @ Xi^T
        launch_bt<EPI_AXPY, false>(pZH, pXiRh, px, 0,
            25, 6, 1, M_, M_, M_, D_, 0,0,0,0,0,0, 1, 0,0,0, ALPHA_);
    }

    // decode
    lnorm_kernel<<<ROWSE, 256>>>(px, pgH, gamma, delta, 1);
    launch_bt<EPI_BIAS, true>(pgH, pdecTh, pdec, dec_b,
        25, 6, 1, D_, D_, D_, D_, 0,0,0,0,0,0, 1, ROWSE, D_, D_, 0.f);
    unpatchify_kernel<<<(B_ * 3 * 224 * 224 + 255) / 256, 256>>>(pdec, out);
}

// round 7
// speedup vs baseline: 5.6808x; 1.2255x over previous
#include <cuda_runtime.h>
#include <cuda_fp16.h>
#include <cstdint>

#define B_      16
#define NP      196
#define NT      197
#define D_      768
#define M_      3072
#define HEADS_  12
#define Y_      64
#define NSTEPS_ 12
#define ALPHA_  0.1f
#define BETA_   0.125f
#define EPS_    1e-5f
#define NMASK_  100
#define RP      3200              // padded row count (25 * 128)
#define QKW     1536              // fused q|k width

// ---------------- scratch (device globals; zero-initialized) ----------------
__device__ __half d_patches[RP*D_];
__device__ float  d_tok[B_*NP*D_];
__device__ float  d_x[RP*D_];
__device__ __half d_g[RP*D_];
__device__ __half d_qk[(RP+64)*QKW];
__device__ __half d_oqk[RP*QKW];
__device__ __half d_Z[RP*M_];
__device__ __half d_W2h[D_*QKW];   // [d][hy|768+hy]   B for backproj (BT)
__device__ __half d_WTh[QKW*D_];   // [hy][d]          B for projection (BT)
__device__ __half d_XiRh[D_*M_];   // Xi               B for hopfield bwd (BT)
__device__ __half d_XiTh[M_*D_];   // Xi^T             B for hopfield fwd (BT)
__device__ __half d_encTh[D_*D_];  // enc_W^T
__device__ __half d_decTh[D_*D_];  // dec_W^T
__device__ float  d_dec[B_*NP*D_];

#define EPI_STORE_S 0
#define EPI_BIAS    1   // float out + bias, guarded rows
#define EPI_RELU_H  2   // half out, relu
#define EPI_AXPY    3   // float out, C += alpha*acc
#define EPI_STORE_H 4   // half out

__device__ __forceinline__ uint32_t smem_u32(const void* p) {
    uint32_t a;
    asm("{ .reg .u64 t; cvta.to.shared.u64 t, %1; cvt.u32.u64 %0, t; }" : "=r"(a) : "l"(p));
    return a;
}
__device__ __forceinline__ void ldsm4(uint32_t* r, uint32_t addr) {
    asm volatile("ldmatrix.sync.aligned.m8n8.x4.shared.b16 {%0,%1,%2,%3}, [%4];"
        : "=r"(r[0]), "=r"(r[1]), "=r"(r[2]), "=r"(r[3]) : "r"(addr));
}
__device__ __forceinline__ void ldsm4t(uint32_t* r, uint32_t addr) {
    asm volatile("ldmatrix.sync.aligned.m8n8.x4.trans.shared.b16 {%0,%1,%2,%3}, [%4];"
        : "=r"(r[0]), "=r"(r[1]), "=r"(r[2]), "=r"(r[3]) : "r"(addr));
}
#define MMA16(acc, a, b0, b1) \
    asm("mma.sync.aligned.m16n8k16.row.col.f32.f16.f16.f32 " \
        "{%0,%1,%2,%3}, {%4,%5,%6,%7}, {%8,%9}, {%0,%1,%2,%3};" \
        : "+f"((acc)[0]), "+f"((acc)[1]), "+f"((acc)[2]), "+f"((acc)[3]) \
        : "r"((a)[0]), "r"((a)[1]), "r"((a)[2]), "r"((a)[3]), "r"(b0), "r"(b1))

// ---- tile loader: 128 rows x 32 halves, smem stride 40 halves ----
__device__ __forceinline__ void ldA16(__half* s, const __half* gp, int ld, int tid) {
    const __half* grow = gp + (long long)tid * ld;
    uint32_t srow = smem_u32(s + tid * 40);
#pragma unroll
    for (int i = 0; i < 4; i++)
        asm volatile("cp.async.cg.shared.global [%0], [%1], 16;"
                     :: "r"(srow + i * 16), "l"(grow + i * 8));
}

// ================= BT fp16 mma GEMM =================
template<int EPI, bool GUARD>
__global__ __launch_bounds__(128, 2) void hbt_kernel(
    const __half* __restrict__ A, const __half* __restrict__ Bm,
    void* __restrict__ Cv, const float* __restrict__ bias,
    int K, int lda, int ldb, int ldc,
    int Mv, int Nv, float alpha)
{
    extern __shared__ __half sh[];
    constexpr int TSZ = 128 * 40;
    __half* sA[2] = { sh,           sh + 2 * TSZ };
    __half* sB[2] = { sh + TSZ,     sh + 3 * TSZ };

    const int tid = threadIdx.x;
    const int lane = tid & 31, wid = tid >> 5;
    const int grp = lane >> 2, tig = lane & 3;
    const int wm = (wid >> 1) * 64, wn = (wid & 1) * 64;
    const long long m0 = (long long)blockIdx.y * 128;
    const long long n0 = (long long)blockIdx.x * 128;
    A += m0 * lda;
    Bm += n0 * ldb;

    const uint32_t laneoff = (lane & 15) * 80 + (lane >> 4) * 16;

    float acc[4][8][4];
#pragma unroll
    for (int i = 0; i < 4; i++)
#pragma unroll
        for (int j = 0; j < 8; j++)
#pragma unroll
            for (int c = 0; c < 4; c++) acc[i][j][c] = 0.f;

    const int nk = K >> 5;
    ldA16(sA[0], A, lda, tid);
    ldA16(sB[0], Bm, ldb, tid);
    asm volatile("cp.async.commit_group;" ::: "memory");

    for (int kt = 0; kt < nk; kt++) {
        if (kt + 1 < nk) {
            int st = (kt + 1) & 1;
            ldA16(sA[st], A + (kt + 1) * 32, lda, tid);
            ldA16(sB[st], Bm + (kt + 1) * 32, ldb, tid);
            asm volatile("cp.async.commit_group;" ::: "memory");
            asm volatile("cp.async.wait_group 1;" ::: "memory");
        } else {
            asm volatile("cp.async.wait_group 0;" ::: "memory");
        }
        __syncthreads();

        const uint32_t aBase = smem_u32(sA[kt & 1]) + wm * 80 + laneoff;
        const uint32_t bBase = smem_u32(sB[kt & 1]) + wn * 80 + laneoff;
#pragma unroll
        for (int kk = 0; kk < 32; kk += 16) {
            uint32_t af[4][4], bp[4][4];
#pragma unroll
            for (int mt = 0; mt < 4; mt++)
                ldsm4(af[mt], aBase + mt * 16 * 80 + kk * 2);
#pragma unroll
            for (int nb = 0; nb < 4; nb++)
                ldsm4(bp[nb], bBase + nb * 16 * 80 + kk * 2);
#pragma unroll
            for (int mt = 0; mt < 4; mt++)
#pragma unroll
                for (int nt = 0; nt < 8; nt++)
                    MMA16(acc[mt][nt], af[mt],
                          bp[nt >> 1][nt & 1], bp[nt >> 1][2 + (nt & 1)]);
        }
        __syncthreads();
    }

    float* Cf = (float*)Cv;
    __half* Ch = (__half*)Cv;
    if (GUARD) {
#pragma unroll
        for (int mt = 0; mt < 4; mt++) {
            long long r0 = m0 + wm + mt * 16 + grp;
#pragma unroll
            for (int nt = 0; nt < 8; nt++) {
                long long c = n0 + wn + nt * 8 + 2 * tig;
#pragma unroll
                for (int e = 0; e < 4; e++) {
                    long long r = r0 + (e >> 1) * 8;
                    long long cc = c + (e & 1);
                    float v = acc[mt][nt][e];
                    if (r < Mv && cc < Nv) {
                        if (EPI == EPI_BIAS) Cf[r * ldc + cc] = v + bias[cc];
                    }
                }
            }
        }
    } else {
#pragma unroll
        for (int mt = 0; mt < 4; mt++) {
            long long r0 = m0 + wm + mt * 16 + grp;
#pragma unroll
            for (int nt = 0; nt < 8; nt++) {
                int col = nt * 8 + 2 * tig;
                float2 v0 = make_float2(acc[mt][nt][0], acc[mt][nt][1]);
                float2 v1 = make_float2(acc[mt][nt][2], acc[mt][nt][3]);
                if (EPI == EPI_AXPY) {
                    float* c0 = Cf + r0 * ldc + n0 + wn + col;
                    float* c1 = c0 + 8LL * ldc;
                    float2 o0 = *(float2*)c0;
                    float2 o1 = *(float2*)c1;
                    o0.x += alpha * v0.x; o0.y += alpha * v0.y;
                    o1.x += alpha * v1.x; o1.y += alpha * v1.y;
                    *(float2*)c0 = o0;
                    *(float2*)c1 = o1;
                } else {
                    __half* c0 = Ch + r0 * ldc + n0 + wn + col;
                    __half* c1 = c0 + 8LL * ldc;
                    if (EPI == EPI_RELU_H) {
                        v0.x = fmaxf(v0.x, 0.f); v0.y = fmaxf(v0.y, 0.f);
                        v1.x = fmaxf(v1.x, 0.f); v1.y = fmaxf(v1.y, 0.f);
                    }
                    *(__half2*)c0 = __floats2half2_rn(v0.x, v0.y);
                    *(__half2*)c1 = __floats2half2_rn(v1.x, v1.y);
                }
            }
        }
    }
}

// ================= fused attention kernel =================
// One CTA per (b,h). smem: sQ[256x72], sK[256x72] halves, sP[128x232] halves.
// Two 128-row blocks: S = q@k^T (fp32 regs) -> softmax -> P (smem fp16)
// -> oq = P@k (store), ok += P^T@q (persistent regs), store ok at end.
__global__ __launch_bounds__(256, 1) void attn_kernel(
    const __half* __restrict__ qk, __half* __restrict__ oqk)
{
    extern __shared__ __half sh[];
    __half* sQ = sh;                   // 256 x 72
    __half* sK = sh + 256 * 72;        // 256 x 72
    __half* sP = sh + 2 * 256 * 72;    // 128 x 232

    const int bh = blockIdx.x;
    const int b = bh / HEADS_, h = bh - b * HEADS_;
    const __half* qbase = qk + (long long)b * NT * QKW + h * 64;
    const __half* kbase = qbase + 768;

    const int tid = threadIdx.x;
    const int lane = tid & 31, w = tid >> 5;
    const int grp = lane >> 2, tig = lane & 3;

    // load q,k rows 0..223 via cp.async; zero rows 224..255
    for (int idx = tid; idx < 224 * 8; idx += 256) {
        int row = idx >> 3, seg = idx & 7;
        uint32_t dq = smem_u32(sQ + row * 72 + seg * 8);
        uint32_t dk = smem_u32(sK + row * 72 + seg * 8);
        asm volatile("cp.async.cg.shared.global [%0], [%1], 16;"
                     :: "r"(dq), "l"(qbase + (long long)row * QKW + seg * 8));
        asm volatile("cp.async.cg.shared.global [%0], [%1], 16;"
                     :: "r"(dk), "l"(kbase + (long long)row * QKW + seg * 8));
    }
    for (int idx = tid; idx < 32 * 36; idx += 256) {
        int row = 224 + idx / 36, c = (idx % 36) * 2;
        *(uint32_t*)(sQ + row * 72 + c) = 0;
        *(uint32_t*)(sK + row * 72 + c) = 0;
    }
    asm volatile("cp.async.commit_group;" ::: "memory");
    asm volatile("cp.async.wait_group 0;" ::: "memory");
    __syncthreads();

    const uint32_t sQ32 = smem_u32(sQ), sK32 = smem_u32(sK), sP32 = smem_u32(sP);
    const uint32_t lm16 = (lane & 15);
    const uint32_t lmHi = (lane >> 4) * 16;

    float okacc[2][8][4];
#pragma unroll
    for (int mt = 0; mt < 2; mt++)
#pragma unroll
        for (int nt = 0; nt < 8; nt++)
#pragma unroll
            for (int e = 0; e < 4; e++) okacc[mt][nt][e] = 0.f;

    for (int blk = 0; blk < 2; blk++) {
        const int row0 = blk * 128;

        // ---- S = q @ k^T for own 16 rows ----
        float sacc[28][4];
#pragma unroll
        for (int nt = 0; nt < 28; nt++)
#pragma unroll
            for (int e = 0; e < 4; e++) sacc[nt][e] = 0.f;

        const uint32_t aBase = sQ32 + (row0 + w * 16 + lm16) * 144 + lmHi;
#pragma unroll
        for (int kc = 0; kc < 4; kc++) {
            uint32_t aq[4];
            ldsm4(aq, aBase + kc * 32);
#pragma unroll
            for (int nb = 0; nb < 14; nb++) {
                uint32_t bp[4];
                ldsm4(bp, sK32 + (nb * 16 + lm16) * 144 + lmHi + kc * 32);
                MMA16(sacc[2 * nb],     aq, bp[0], bp[2]);
                MMA16(sacc[2 * nb + 1], aq, bp[1], bp[3]);
            }
        }

        // ---- softmax over full rows (cols >= 197 masked) ----
        float m0 = -1e30f, m1 = -1e30f;
#pragma unroll
        for (int nt = 0; nt < 28; nt++) {
            int c0 = nt * 8 + 2 * tig;
            if (c0 >= NT)     { sacc[nt][0] = -1e30f; sacc[nt][2] = -1e30f; }
            if (c0 + 1 >= NT) { sacc[nt][1] = -1e30f; sacc[nt][3] = -1e30f; }
            m0 = fmaxf(m0, fmaxf(sacc[nt][0], sacc[nt][1]));
            m1 = fmaxf(m1, fmaxf(sacc[nt][2], sacc[nt][3]));
        }
        m0 = fmaxf(m0, __shfl_xor_sync(0xffffffffu, m0, 1));
        m0 = fmaxf(m0, __shfl_xor_sync(0xffffffffu, m0, 2));
        m1 = fmaxf(m1, __shfl_xor_sync(0xffffffffu, m1, 1));
        m1 = fmaxf(m1, __shfl_xor_sync(0xffffffffu, m1, 2));
        float s0 = 0.f, s1 = 0.f;
#pragma unroll
        for (int nt = 0; nt < 28; nt++) {
            sacc[nt][0] = __expf(BETA_ * (sacc[nt][0] - m0));
            sacc[nt][1] = __expf(BETA_ * (sacc[nt][1] - m0));
            sacc[nt][2] = __expf(BETA_ * (sacc[nt][2] - m1));
            sacc[nt][3] = __expf(BETA_ * (sacc[nt][3] - m1));
            s0 += sacc[nt][0] + sacc[nt][1];
            s1 += sacc[nt][2] + sacc[nt][3];
        }
        s0 += __shfl_xor_sync(0xffffffffu, s0, 1);
        s0 += __shfl_xor_sync(0xffffffffu, s0, 2);
        s1 += __shfl_xor_sync(0xffffffffu, s1, 1);
        s1 += __shfl_xor_sync(0xffffffffu, s1, 2);
        float i0 = 1.f / s0, i1 = 1.f / s1;

        // store P block to smem (rows >= 197 zeroed)
        const int rl = w * 16 + grp;
        const bool rv0 = (row0 + rl) < NT;
        const bool rv1 = (row0 + rl + 8) < NT;
#pragma unroll
        for (int nt = 0; nt < 28; nt++) {
            __half2 h0 = rv0 ? __floats2half2_rn(sacc[nt][0] * i0, sacc[nt][1] * i0)
                             : __floats2half2_rn(0.f, 0.f);
            __half2 h1 = rv1 ? __floats2half2_rn(sacc[nt][2] * i1, sacc[nt][3] * i1)
                             : __floats2half2_rn(0.f, 0.f);
            *(__half2*)(sP + rl * 232 + nt * 8 + 2 * tig) = h0;
            *(__half2*)(sP + (rl + 8) * 232 + nt * 8 + 2 * tig) = h1;
        }
        __syncthreads();

        // ---- oq = P @ k (own 16 rows) ----
        float oqa[8][4];
#pragma unroll
        for (int nt = 0; nt < 8; nt++)
#pragma unroll
            for (int e = 0; e < 4; e++) oqa[nt][e] = 0.f;

        const uint32_t aPq = sP32 + (w * 16 + lm16) * 464 + lmHi;
#pragma unroll
        for (int mc = 0; mc < 14; mc++) {
            uint32_t ap[4];
            ldsm4(ap, aPq + mc * 32);
            uint32_t bq[4][4];
#pragma unroll
            for (int yb = 0; yb < 4; yb++)
                ldsm4t(bq[yb], sK32 + (mc * 16 + lm16) * 144 + lmHi + yb * 32);
#pragma unroll
            for (int nt = 0; nt < 8; nt++)
                MMA16(oqa[nt], ap, bq[nt >> 1][(nt & 1) * 2], bq[nt >> 1][(nt & 1) * 2 + 1]);
        }
        {
            int gr = row0 + w * 16 + grp;
            if (gr < NT) {
                __half* dst = oqk + ((long long)(b * NT + gr)) * QKW + h * 64;
#pragma unroll
                for (int nt = 0; nt < 8; nt++)
                    *(__half2*)(dst + nt * 8 + 2 * tig) = __floats2half2_rn(oqa[nt][0], oqa[nt][1]);
            }
            if (gr + 8 < NT) {
                __half* dst = oqk + ((long long)(b * NT + gr + 8)) * QKW + h * 64;
#pragma unroll
                for (int nt = 0; nt < 8; nt++)
                    *(__half2*)(dst + nt * 8 + 2 * tig) = __floats2half2_rn(oqa[nt][2], oqa[nt][3]);
            }
        }

        // ---- ok += P^T @ q (persistent acc) ----
#pragma unroll
        for (int rc = 0; rc < 8; rc++) {
            uint32_t bq[4][4];
#pragma unroll
            for (int yb = 0; yb < 4; yb++)
                ldsm4t(bq[yb], sQ32 + (row0 + rc * 16 + lm16) * 144 + lmHi + yb * 32);
#pragma unroll
            for (int mt = 0; mt < 2; mt++) {
                if (mt == 0 || w < 6) {
                    int t = w + mt * 8;
                    uint32_t tmp[4];
                    ldsm4t(tmp, sP32 + (rc * 16 + lm16) * 464 + lmHi + t * 32);
                    uint32_t ap[4] = { tmp[0], tmp[2], tmp[1], tmp[3] };
#pragma unroll
                    for (int nt = 0; nt < 8; nt++)
                        MMA16(okacc[mt][nt], ap,
                              bq[nt >> 1][(nt & 1) * 2], bq[nt >> 1][(nt & 1) * 2 + 1]);
                }
            }
        }
        __syncthreads();
    }

    // ---- store ok ----
#pragma unroll
    for (int mt = 0; mt < 2; mt++) {
        if (mt == 0 || w < 6) {
            int t = w + mt * 8;
            int c0 = t * 16 + grp;
            if (c0 < NT) {
                __half* dst = oqk + ((long long)(b * NT + c0)) * QKW + 768 + h * 64;
#pragma unroll
                for (int nt = 0; nt < 8; nt++)
                    *(__half2*)(dst + nt * 8 + 2 * tig) = __floats2half2_rn(okacc[mt][nt][0], okacc[mt][nt][1]);
            }
            if (c0 + 8 < NT) {
                __half* dst = oqk + ((long long)(b * NT + c0 + 8)) * QKW + 768 + h * 64;
#pragma unroll
                for (int nt = 0; nt < 8; nt++)
                    *(__half2*)(dst + nt * 8 + 2 * tig) = __floats2half2_rn(okacc[mt][nt][2], okacc[mt][nt][3]);
            }
        }
    }
}

// ================= layernorm (fp32 in, half out) =================
__device__ __forceinline__ float block_sum256(float v, float* red) {
    int lane = threadIdx.x & 31, w = threadIdx.x >> 5;
#pragma unroll
    for (int o = 16; o > 0; o >>= 1) v += __shfl_xor_sync(0xffffffffu, v, o);
    if (lane == 0) red[w] = v;
    __syncthreads();
    float s = 0.f;
#pragma unroll
    for (int i = 0; i < 8; i++) s += red[i];
    __syncthreads();
    return s;
}

__global__ void lnorm_kernel(const float* __restrict__ x, __half* __restrict__ g,
                             const float* __restrict__ gamma_p,
                             const float* __restrict__ delta, int skipcls)
{
    __shared__ float red[8];
    int r = blockIdx.x;
    const float* xr;
    __half* gr;
    if (skipcls) {
        int b = r / NP, i = r - b * NP;
        xr = x + (long long)(b * NT + 1 + i) * D_;
        gr = g + (long long)r * D_;
    } else {
        xr = x + (long long)r * D_;
        gr = g + (long long)r * D_;
    }
    int t = threadIdx.x; // 256
    float v0 = xr[t], v1 = xr[t + 256], v2 = xr[t + 512];
    float mean = block_sum256(v0 + v1 + v2, red) * (1.f / 768.f);
    float c0 = v0 - mean, c1 = v1 - mean, c2 = v2 - mean;
    float var = block_sum256(c0*c0 + c1*c1 + c2*c2, red) * (1.f / 768.f);
    float rinv = rsqrtf(var + EPS_);
    float gm = gamma_p[0];
    gr[t]       = __float2half(gm * c0 * rinv + delta[t]);
    gr[t + 256] = __float2half(gm * c1 * rinv + delta[t + 256]);
    gr[t + 512] = __float2half(gm * c2 * rinv + delta[t + 512]);
}

// ================= weight prep =================
__global__ void build_wqk_kernel(const float* __restrict__ Wq, const float* __restrict__ Wk,
                                 __half* __restrict__ W2, __half* __restrict__ WT)
{
    int idx = blockIdx.x * 256 + threadIdx.x;
    if (idx >= 2 * D_ * D_) return;
    int which = idx >= D_ * D_;
    int r = idx - which * D_ * D_;
    int h = r / (D_ * Y_);
    int rem = r - h * (D_ * Y_);
    int d = rem / Y_;
    int y = rem - d * Y_;
    __half v = __float2half(which ? Wk[r] : Wq[r]);
    int hy = h * Y_ + y + which * D_;
    W2[d * QKW + hy] = v;
    WT[(long long)hy * D_ + d] = v;
}

__global__ void build_xi_kernel(const float* __restrict__ Xi,
                                __half* __restrict__ XiR, __half* __restrict__ XiT)
{
    __shared__ __half t[32][33];
    int d0 = blockIdx.y * 32, m0 = blockIdx.x * 32;
    int tx = threadIdx.x & 31, ty = threadIdx.x >> 5;
#pragma unroll
    for (int i = 0; i < 32; i += 8) {
        __half v = __float2half(Xi[(long long)(d0 + ty + i) * M_ + m0 + tx]);
        XiR[(long long)(d0 + ty + i) * M_ + m0 + tx] = v;
        t[ty + i][tx] = v;
    }
    __syncthreads();
#pragma unroll
    for (int i = 0; i < 32; i += 8)
        XiT[(long long)(m0 + ty + i) * D_ + d0 + tx] = t[tx][ty + i];
}

__global__ void build_wt_kernel(const float* __restrict__ W, __half* __restrict__ WT)
{
    __shared__ __half t[32][33];
    int i0 = blockIdx.y * 32, j0 = blockIdx.x * 32;
    int tx = threadIdx.x & 31, ty = threadIdx.x >> 5;
#pragma unroll
    for (int i = 0; i < 32; i += 8)
        t[ty + i][tx] = __float2half(W[(long long)(i0 + ty + i) * D_ + j0 + tx]);
    __syncthreads();
#pragma unroll
    for (int i = 0; i < 32; i += 8)
        WT[(long long)(j0 + ty + i) * D_ + i0 + tx] = t[tx][ty + i];
}

// ================= misc =================
__global__ void patchify_kernel(const float* __restrict__ img, __half* __restrict__ out)
{
    int idx = blockIdx.x * 256 + threadIdx.x;
    if (idx >= B_ * NP * D_) return;
    int e = idx % D_;
    int rest = idx / D_;
    int p = rest % NP;
    int b = rest / NP;
    int c = e >> 8;
    int r = (e >> 4) & 15;
    int col = e & 15;
    int kh = p / 14, kw = p - kh * 14;
    out[idx] = __float2half(img[((long long)(b * 3 + c) * 224 + kh * 16 + r) * 224 + kw * 16 + col]);
}

__global__ void unpatchify_kernel(const float* __restrict__ dec, float* __restrict__ out)
{
    int idx = blockIdx.x * 256 + threadIdx.x;
    if (idx >= B_ * 3 * 224 * 224) return;
    int w = idx % 224;
    int rest = idx / 224;
    int h = rest % 224;
    rest /= 224;
    int c = rest % 3;
    int b = rest / 3;
    int kh = h >> 4, r = h & 15, kw = w >> 4, col = w & 15;
    out[idx] = dec[(long long)(b * NP + kh * 14 + kw) * D_ + c * 256 + r * 16 + col];
}

__global__ void build_x_kernel(const float* __restrict__ tok, const int* __restrict__ mask,
                               const float* __restrict__ cls, const float* __restrict__ mtok,
                               const float* __restrict__ pos, float* __restrict__ x)
{
    __shared__ int sm[NP];
    __shared__ unsigned char flag[NP];
    __shared__ int count_s;
    int b = blockIdx.x;
    int t = threadIdx.x; // 256
    if (t < NP) sm[t] = mask[b * NP + t];
    __syncthreads();
    if (t < NP) {
        int pref = 0;
        for (int j = 0; j < t; j++) pref += (sm[j] == 1);
        flag[t] = (sm[t] == 1 && pref < NMASK_) ? 1 : 0;
        if (t == NP - 1) count_s = pref + (sm[t] == 1);
    }
    __syncthreads();
    if (t == 0 && count_s < NMASK_) flag[0] = 1; // fill_value=0 padding hits token 0
    __syncthreads();
    for (int tk = 0; tk < NT; tk++) {
        const float* src;
        if (tk == 0) src = cls;
        else if (flag[tk - 1]) src = mtok;
        else src = tok + (long long)(b * NP + tk - 1) * D_;
        float* dst = x + (long long)(b * NT + tk) * D_;
        const float* pr = pos + (long long)tk * D_;
        for (int d = t; d < D_; d += 256) dst[d] = src[d] + pr[d];
    }
}

// ================= host wrappers =================
template<int EPI, bool GUARD>
static void launch_bt(const __half* A, const __half* B, void* C, const float* bias,
                      int Mtiles, int Ntiles, int K,
                      int lda, int ldb, int ldc,
                      int Mv, int Nv, float alpha)
{
    int smem = 4 * 128 * 40 * 2;   // 40960
    cudaFuncSetAttribute(hbt_kernel<EPI, GUARD>,
                         cudaFuncAttributeMaxDynamicSharedMemorySize, smem);
    dim3 g(Ntiles, Mtiles, 1);
    hbt_kernel<EPI, GUARD><<<g, 128, smem>>>(A, B, C, bias, K, lda, ldb, ldc,
                                             Mv, Nv, alpha);
}

extern "C" void kernel_launch(void* const* d_in, const int* in_sizes, int n_in,
                              void* d_out, int out_size)
{
    const float* img   = (const float*)d_in[0];
    const int*   mask  = (const int*)  d_in[1];
    const float* enc_W = (const float*)d_in[2];
    const float* enc_b = (const float*)d_in[3];
    const float* dec_W = (const float*)d_in[4];
    const float* dec_b = (const float*)d_in[5];
    const float* cls   = (const float*)d_in[6];
    const float* mtok  = (const float*)d_in[7];
    const float* pos   = (const float*)d_in[8];
    const float* Wq    = (const float*)d_in[9];
    const float* Wk    = (const float*)d_in[10];
    const float* Xi    = (const float*)d_in[11];
    const float* gamma = (const float*)d_in[12];
    const float* delta = (const float*)d_in[13];
    float* out = (float*)d_out;

    __half *ppatH, *pgH, *pqkH, *poqkH, *pZH;
    __half *pW2h, *pWTh, *pXiRh, *pXiTh, *pencTh, *pdecTh;
    float *ptok, *px, *pdec;
    cudaGetSymbolAddress((void**)&ppatH, d_patches);
    cudaGetSymbolAddress((void**)&ptok,  d_tok);
    cudaGetSymbolAddress((void**)&px,    d_x);
    cudaGetSymbolAddress((void**)&pgH,   d_g);
    cudaGetSymbolAddress((void**)&pqkH,  d_qk);
    cudaGetSymbolAddress((void**)&poqkH, d_oqk);
    cudaGetSymbolAddress((void**)&pZH,   d_Z);
    cudaGetSymbolAddress((void**)&pW2h,  d_W2h);
    cudaGetSymbolAddress((void**)&pWTh,  d_WTh);
    cudaGetSymbolAddress((void**)&pXiRh, d_XiRh);
    cudaGetSymbolAddress((void**)&pXiTh, d_XiTh);
    cudaGetSymbolAddress((void**)&pencTh, d_encTh);
    cudaGetSymbolAddress((void**)&pdecTh, d_decTh);
    cudaGetSymbolAddress((void**)&pdec,  d_dec);

    const int ROWS  = B_ * NT;   // 3152
    const int ROWSE = B_ * NP;   // 3136

    // weight prep
    build_wqk_kernel<<<(2 * D_ * D_ + 255) / 256, 256>>>(Wq, Wk, pW2h, pWTh);
    build_xi_kernel<<<dim3(M_ / 32, D_ / 32), 256>>>(Xi, pXiRh, pXiTh);
    build_wt_kernel<<<dim3(24, 24), 256>>>(enc_W, pencTh);
    build_wt_kernel<<<dim3(24, 24), 256>>>(dec_W, pdecTh);

    // encode
    patchify_kernel<<<(B_ * NP * D_ + 255) / 256, 256>>>(img, ppatH);
    launch_bt<EPI_BIAS, true>(ppatH, pencTh, ptok, enc_b,
        25, 6, D_, D_, D_, D_, ROWSE, D_, 0.f);
    build_x_kernel<<<B_, 256>>>(ptok, mask, cls, mtok, pos, px);

    int attn_smem = (2 * 256 * 72 + 128 * 232) * 2;   // 133120
    cudaFuncSetAttribute(attn_kernel,
                         cudaFuncAttributeMaxDynamicSharedMemorySize, attn_smem);

    for (int s = 0; s < NSTEPS_; s++) {
        lnorm_kernel<<<ROWS, 256>>>(px, pgH, gamma, delta, 0);
        // q|k = g @ WT^T
        launch_bt<EPI_STORE_H, false>(pgH, pWTh, pqkH, 0,
            25, 12, D_, D_, D_, QKW, 0, 0, 0.f);
        // fused attention: oqk <- [P@k | P^T@q]
        attn_kernel<<<B_ * HEADS_, 256, attn_smem>>>(pqkH, poqkH);
        // x += alpha * [oq|ok] @ W2
        launch_bt<EPI_AXPY, false>(poqkH, pW2h, px, 0,
            25, 6, QKW, QKW, QKW, D_, 0, 0, ALPHA_);
        // Z = relu(g @ Xi)
        launch_bt<EPI_RELU_H, false>(pgH, pXiTh, pZH, 0,
            25, 24, D_, D_, D_, M_, 0, 0, 0.f);
        // x += alpha * Z @ Xi^T
        launch_bt<EPI_AXPY, false>(pZH, pXiRh, px, 0,
            25, 6, M_, M_, M_, D_, 0, 0, ALPHA_);
    }

    // decode
    lnorm_kernel<<<ROWSE, 256>>>(px, pgH, gamma, delta, 1);
    launch_bt<EPI_BIAS, true>(pgH, pdecTh, pdec, dec_b,
        25, 6, D_, D_, D_, D_, ROWSE, D_, 0.f);
    unpatchify_kernel<<<(B_ * 3 * 224 * 224 + 255) / 256, 256>>>(pdec, out);
}

// round 9
// speedup vs baseline: 7.6578x; 1.3480x over previous
#include <cuda_runtime.h>
#include <cuda_fp16.h>
#include <cstdint>

#define B_      16
#define NP      196
#define NT      197
#define D_      768
#define M_      3072
#define HEADS_  12
#define Y_      64
#define NSTEPS_ 12
#define ALPHA_  0.1f
#define BETA_   0.125f
#define EPS_    1e-5f
#define NMASK_  100
#define RP      3200              // padded row count (25 * 128)
#define QKW     1536              // q|k width
#define ACTW    4608              // [oq|ok|Z] fused activation width
#define FW      4608              // fused fwd output width (q|k|Z)

// ---------------- scratch (device globals; zero-initialized) ----------------
__device__ __half d_patches[RP*D_];
__device__ float  d_tok[B_*NP*D_];
__device__ float  d_x[RP*D_];
__device__ __half d_g[RP*D_];
__device__ __half d_qk[(RP+64)*QKW];
__device__ __half d_act[RP*ACTW];     // cols 0..1535 = [oq|ok], 1536.. = Z
__device__ __half d_Wfwd[FW*D_];      // rows: [WT (hy) | XiT (mu)]; k-major d
__device__ __half d_Wback[D_*ACTW];   // [d][hy | 1536+mu]
__device__ __half d_encTh[D_*D_];
__device__ __half d_decTh[D_*D_];
__device__ float  d_dec[B_*NP*D_];

#define EPI_BIAS    1   // float out + bias, guarded rows
#define EPI_AXPY    3   // float out, C += alpha*acc
#define EPI_QKZ     5   // dual: n0<1536 -> half store to Cv (ld 1536); else relu half to Cv2 (ld 4608)

__device__ __forceinline__ uint32_t smem_u32(const void* p) {
    uint32_t a;
    asm("{ .reg .u64 t; cvta.to.shared.u64 t, %1; cvt.u32.u64 %0, t; }" : "=r"(a) : "l"(p));
    return a;
}
__device__ __forceinline__ void ldsm4(uint32_t* r, uint32_t addr) {
    asm volatile("ldmatrix.sync.aligned.m8n8.x4.shared.b16 {%0,%1,%2,%3}, [%4];"
        : "=r"(r[0]), "=r"(r[1]), "=r"(r[2]), "=r"(r[3]) : "r"(addr));
}
__device__ __forceinline__ void ldsm4t(uint32_t* r, uint32_t addr) {
    asm volatile("ldmatrix.sync.aligned.m8n8.x4.trans.shared.b16 {%0,%1,%2,%3}, [%4];"
        : "=r"(r[0]), "=r"(r[1]), "=r"(r[2]), "=r"(r[3]) : "r"(addr));
}
#define MMA16(acc, a, b0, b1) \
    asm("mma.sync.aligned.m16n8k16.row.col.f32.f16.f16.f32 " \
        "{%0,%1,%2,%3}, {%4,%5,%6,%7}, {%8,%9}, {%0,%1,%2,%3};" \
        : "+f"((acc)[0]), "+f"((acc)[1]), "+f"((acc)[2]), "+f"((acc)[3]) \
        : "r"((a)[0]), "r"((a)[1]), "r"((a)[2]), "r"((a)[3]), "r"(b0), "r"(b1))

// ---- generic tile loader: R rows x 32 halves, smem stride 40 ----
template<int R>
__device__ __forceinline__ void ldTile(__half* s, const __half* gp, int ld, int tid) {
#pragma unroll
    for (int i = 0; i < R / 32; i++) {
        int idx = tid + 128 * i;
        int row = idx >> 2, seg = idx & 3;
        asm volatile("cp.async.cg.shared.global [%0], [%1], 16;"
                     :: "r"(smem_u32(s + row * 40 + seg * 8)),
                        "l"(gp + (long long)row * ld + seg * 8));
    }
}

// ================= BT fp16 mma GEMM, 3-stage pipeline =================
// C[m,n] (op)= sum_k A[m,k]*B[n,k]; both k-major. Block (WM*32)x128, 4 warps.
template<int EPI, int WM, bool GUARD>
__global__ __launch_bounds__(128, 2) void hbt_kernel(
    const __half* __restrict__ A, const __half* __restrict__ Bm,
    void* __restrict__ Cv, void* __restrict__ Cv2,
    const float* __restrict__ bias,
    int K, int lda, int ldb, int ldc,
    int Mv, int Nv, float alpha)
{
    extern __shared__ __half sh[];
    constexpr int AR  = WM * 32;
    constexpr int STG = (AR + 128) * 40;
    __half* sA[3] = { sh, sh + STG, sh + 2 * STG };
    __half* sB[3] = { sh + AR * 40, sh + STG + AR * 40, sh + 2 * STG + AR * 40 };

    const int tid = threadIdx.x;
    const int lane = tid & 31, wid = tid >> 5;
    const int grp = lane >> 2, tig = lane & 3;
    const int wm = (wid >> 1) * (WM * 16), wn = (wid & 1) * 64;
    const long long m0 = (long long)blockIdx.y * AR;
    const long long n0 = (long long)blockIdx.x * 128;
    A += m0 * lda;
    Bm += n0 * ldb;

    const uint32_t laneoff = (lane & 15) * 80 + (lane >> 4) * 16;

    float acc[WM][8][4];
#pragma unroll
    for (int i = 0; i < WM; i++)
#pragma unroll
        for (int j = 0; j < 8; j++)
#pragma unroll
            for (int c = 0; c < 4; c++) acc[i][j][c] = 0.f;

    const int nk = K >> 5;   // always >= 24 here
    ldTile<AR>(sA[0], A, lda, tid);
    ldTile<128>(sB[0], Bm, ldb, tid);
    asm volatile("cp.async.commit_group;" ::: "memory");
    ldTile<AR>(sA[1], A + 32, lda, tid);
    ldTile<128>(sB[1], Bm + 32, ldb, tid);
    asm volatile("cp.async.commit_group;" ::: "memory");

    int st = 0;
    for (int kt = 0; kt < nk; kt++) {
        if (kt + 1 < nk)
            asm volatile("cp.async.wait_group 1;" ::: "memory");
        else
            asm volatile("cp.async.wait_group 0;" ::: "memory");
        __syncthreads();

        if (kt + 2 < nk) {
            int ls = st + 2; if (ls >= 3) ls -= 3;
            ldTile<AR>(sA[ls], A + (kt + 2) * 32, lda, tid);
            ldTile<128>(sB[ls], Bm + (kt + 2) * 32, ldb, tid);
            asm volatile("cp.async.commit_group;" ::: "memory");
        }

        const uint32_t aBase = smem_u32(sA[st]) + wm * 80 + laneoff;
        const uint32_t bBase = smem_u32(sB[st]) + wn * 80 + laneoff;
#pragma unroll
        for (int kk = 0; kk < 32; kk += 16) {
            uint32_t af[WM][4], bp[4][4];
#pragma unroll
            for (int mt = 0; mt < WM; mt++)
                ldsm4(af[mt], aBase + mt * 16 * 80 + kk * 2);
#pragma unroll
            for (int nb = 0; nb < 4; nb++)
                ldsm4(bp[nb], bBase + nb * 16 * 80 + kk * 2);
#pragma unroll
            for (int mt = 0; mt < WM; mt++)
#pragma unroll
                for (int nt = 0; nt < 8; nt++)
                    MMA16(acc[mt][nt], af[mt],
                          bp[nt >> 1][nt & 1], bp[nt >> 1][2 + (nt & 1)]);
        }
        st = (st + 1 == 3) ? 0 : st + 1;
    }

    // ---- epilogues ----
    if (EPI == EPI_QKZ) {
        bool isqk = (n0 < 1536);
        __half* base = isqk ? ((__half*)Cv + n0) : ((__half*)Cv2 + n0);
        int ldx = isqk ? 1536 : ACTW;
#pragma unroll
        for (int mt = 0; mt < WM; mt++) {
            long long r0 = m0 + wm + mt * 16 + grp;
#pragma unroll
            for (int nt = 0; nt < 8; nt++) {
                int col = wn + nt * 8 + 2 * tig;
                float2 v0 = make_float2(acc[mt][nt][0], acc[mt][nt][1]);
                float2 v1 = make_float2(acc[mt][nt][2], acc[mt][nt][3]);
                if (!isqk) {
                    v0.x = fmaxf(v0.x, 0.f); v0.y = fmaxf(v0.y, 0.f);
                    v1.x = fmaxf(v1.x, 0.f); v1.y = fmaxf(v1.y, 0.f);
                }
                *(__half2*)(base + r0 * ldx + col) = __floats2half2_rn(v0.x, v0.y);
                *(__half2*)(base + (r0 + 8) * ldx + col) = __floats2half2_rn(v1.x, v1.y);
            }
        }
    } else if (GUARD) {
        float* Cf = (float*)Cv;
#pragma unroll
        for (int mt = 0; mt < WM; mt++) {
            long long r0 = m0 + wm + mt * 16 + grp;
#pragma unroll
            for (int nt = 0; nt < 8; nt++) {
                long long c = n0 + wn + nt * 8 + 2 * tig;
#pragma unroll
                for (int e = 0; e < 4; e++) {
                    long long r = r0 + (e >> 1) * 8;
                    long long cc = c + (e & 1);
                    if (r < Mv && cc < Nv)
                        Cf[r * ldc + cc] = acc[mt][nt][e] + bias[cc];
                }
            }
        }
    } else {  // EPI_AXPY
        float* Cf = (float*)Cv;
#pragma unroll
        for (int mt = 0; mt < WM; mt++) {
            long long r0 = m0 + wm + mt * 16 + grp;
#pragma unroll
            for (int nt = 0; nt < 8; nt++) {
                int col = nt * 8 + 2 * tig;
                float* c0 = Cf + r0 * ldc + n0 + wn + col;
                float* c1 = c0 + 8LL * ldc;
                float2 o0 = *(float2*)c0;
                float2 o1 = *(float2*)c1;
                o0.x += alpha * acc[mt][nt][0]; o0.y += alpha * acc[mt][nt][1];
                o1.x += alpha * acc[mt][nt][2]; o1.y += alpha * acc[mt][nt][3];
                *(float2*)c0 = o0;
                *(float2*)c1 = o1;
            }
        }
    }
}

// ================= fused attention kernel =================
// One CTA per (b,h). Reads q,k from d_qk (stride 1536); writes oq/ok into
// d_act (stride 4608, cols h*64 and 768+h*64).
__global__ __launch_bounds__(256, 1) void attn_kernel(
    const __half* __restrict__ qk, __half* __restrict__ act)
{
    extern __shared__ __half sh[];
    __half* sQ = sh;                   // 256 x 72
    __half* sK = sh + 256 * 72;        // 256 x 72
    __half* sP = sh + 2 * 256 * 72;    // 128 x 232

    const int bh = blockIdx.x;
    const int b = bh / HEADS_, h = bh - b * HEADS_;
    const __half* qbase = qk + (long long)b * NT * QKW + h * 64;
    const __half* kbase = qbase + 768;

    const int tid = threadIdx.x;
    const int lane = tid & 31, w = tid >> 5;
    const int grp = lane >> 2, tig = lane & 3;

    for (int idx = tid; idx < 224 * 8; idx += 256) {
        int row = idx >> 3, seg = idx & 7;
        asm volatile("cp.async.cg.shared.global [%0], [%1], 16;"
                     :: "r"(smem_u32(sQ + row * 72 + seg * 8)),
                        "l"(qbase + (long long)row * QKW + seg * 8));
        asm volatile("cp.async.cg.shared.global [%0], [%1], 16;"
                     :: "r"(smem_u32(sK + row * 72 + seg * 8)),
                        "l"(kbase + (long long)row * QKW + seg * 8));
    }
    for (int idx = tid; idx < 32 * 36; idx += 256) {
        int row = 224 + idx / 36, c = (idx % 36) * 2;
        *(uint32_t*)(sQ + row * 72 + c) = 0;
        *(uint32_t*)(sK + row * 72 + c) = 0;
    }
    asm volatile("cp.async.commit_group;" ::: "memory");
    asm volatile("cp.async.wait_group 0;" ::: "memory");
    __syncthreads();

    const uint32_t sQ32 = smem_u32(sQ), sK32 = smem_u32(sK), sP32 = smem_u32(sP);
    const uint32_t lm16 = (lane & 15);
    const uint32_t lmHi = (lane >> 4) * 16;

    float okacc[2][8][4];
#pragma unroll
    for (int mt = 0; mt < 2; mt++)
#pragma unroll
        for (int nt = 0; nt < 8; nt++)
#pragma unroll
            for (int e = 0; e < 4; e++) okacc[mt][nt][e] = 0.f;

    for (int blk = 0; blk < 2; blk++) {
        const int row0 = blk * 128;

        float sacc[28][4];
#pragma unroll
        for (int nt = 0; nt < 28; nt++)
#pragma unroll
            for (int e = 0; e < 4; e++) sacc[nt][e] = 0.f;

        const uint32_t aBase = sQ32 + (row0 + w * 16 + lm16) * 144 + lmHi;
#pragma unroll
        for (int kc = 0; kc < 4; kc++) {
            uint32_t aq[4];
            ldsm4(aq, aBase + kc * 32);
#pragma unroll
            for (int nb = 0; nb < 14; nb++) {
                uint32_t bp[4];
                ldsm4(bp, sK32 + (nb * 16 + lm16) * 144 + lmHi + kc * 32);
                MMA16(sacc[2 * nb],     aq, bp[0], bp[2]);
                MMA16(sacc[2 * nb + 1], aq, bp[1], bp[3]);
            }
        }

        float m0 = -1e30f, m1 = -1e30f;
#pragma unroll
        for (int nt = 0; nt < 28; nt++) {
            int c0 = nt * 8 + 2 * tig;
            if (c0 >= NT)     { sacc[nt][0] = -1e30f; sacc[nt][2] = -1e30f; }
            if (c0 + 1 >= NT) { sacc[nt][1] = -1e30f; sacc[nt][3] = -1e30f; }
            m0 = fmaxf(m0, fmaxf(sacc[nt][0], sacc[nt][1]));
            m1 = fmaxf(m1, fmaxf(sacc[nt][2], sacc[nt][3]));
        }
        m0 = fmaxf(m0, __shfl_xor_sync(0xffffffffu, m0, 1));
        m0 = fmaxf(m0, __shfl_xor_sync(0xffffffffu, m0, 2));
        m1 = fmaxf(m1, __shfl_xor_sync(0xffffffffu, m1, 1));
        m1 = fmaxf(m1, __shfl_xor_sync(0xffffffffu, m1, 2));
        float s0 = 0.f, s1 = 0.f;
#pragma unroll
        for (int nt = 0; nt < 28; nt++) {
            sacc[nt][0] = __expf(BETA_ * (sacc[nt][0] - m0));
            sacc[nt][1] = __expf(BETA_ * (sacc[nt][1] - m0));
            sacc[nt][2] = __expf(BETA_ * (sacc[nt][2] - m1));
            sacc[nt][3] = __expf(BETA_ * (sacc[nt][3] - m1));
            s0 += sacc[nt][0] + sacc[nt][1];
            s1 += sacc[nt][2] + sacc[nt][3];
        }
        s0 += __shfl_xor_sync(0xffffffffu, s0, 1);
        s0 += __shfl_xor_sync(0xffffffffu, s0, 2);
        s1 += __shfl_xor_sync(0xffffffffu, s1, 1);
        s1 += __shfl_xor_sync(0xffffffffu, s1, 2);
        float i0 = 1.f / s0, i1 = 1.f / s1;

        const int rl = w * 16 + grp;
        const bool rv0 = (row0 + rl) < NT;
        const bool rv1 = (row0 + rl + 8) < NT;
#pragma unroll
        for (int nt = 0; nt < 28; nt++) {
            __half2 h0 = rv0 ? __floats2half2_rn(sacc[nt][0] * i0, sacc[nt][1] * i0)
                             : __floats2half2_rn(0.f, 0.f);
            __half2 h1 = rv1 ? __floats2half2_rn(sacc[nt][2] * i1, sacc[nt][3] * i1)
                             : __floats2half2_rn(0.f, 0.f);
            *(__half2*)(sP + rl * 232 + nt * 8 + 2 * tig) = h0;
            *(__half2*)(sP + (rl + 8) * 232 + nt * 8 + 2 * tig) = h1;
        }
        __syncthreads();

        // oq = P @ k
        float oqa[8][4];
#pragma unroll
        for (int nt = 0; nt < 8; nt++)
#pragma unroll
            for (int e = 0; e < 4; e++) oqa[nt][e] = 0.f;

        const uint32_t aPq = sP32 + (w * 16 + lm16) * 464 + lmHi;
#pragma unroll
        for (int mc = 0; mc < 14; mc++) {
            uint32_t ap[4];
            ldsm4(ap, aPq + mc * 32);
            uint32_t bq[4][4];
#pragma unroll
            for (int yb = 0; yb < 4; yb++)
                ldsm4t(bq[yb], sK32 + (mc * 16 + lm16) * 144 + lmHi + yb * 32);
#pragma unroll
            for (int nt = 0; nt < 8; nt++)
                MMA16(oqa[nt], ap, bq[nt >> 1][(nt & 1) * 2], bq[nt >> 1][(nt & 1) * 2 + 1]);
        }
        {
            int gr = row0 + w * 16 + grp;
            if (gr < NT) {
                __half* dst = act + ((long long)(b * NT + gr)) * ACTW + h * 64;
#pragma unroll
                for (int nt = 0; nt < 8; nt++)
                    *(__half2*)(dst + nt * 8 + 2 * tig) = __floats2half2_rn(oqa[nt][0], oqa[nt][1]);
            }
            if (gr + 8 < NT) {
                __half* dst = act + ((long long)(b * NT + gr + 8)) * ACTW + h * 64;
#pragma unroll
                for (int nt = 0; nt < 8; nt++)
                    *(__half2*)(dst + nt * 8 + 2 * tig) = __floats2half2_rn(oqa[nt][2], oqa[nt][3]);
            }
        }

        // ok += P^T @ q
#pragma unroll
        for (int rc = 0; rc < 8; rc++) {
            uint32_t bq[4][4];
#pragma unroll
            for (int yb = 0; yb < 4; yb++)
                ldsm4t(bq[yb], sQ32 + (row0 + rc * 16 + lm16) * 144 + lmHi + yb * 32);
#pragma unroll
            for (int mt = 0; mt < 2; mt++) {
                if (mt == 0 || w < 6) {
                    int t = w + mt * 8;
                    uint32_t tmp[4];
                    ldsm4t(tmp, sP32 + (rc * 16 + lm16) * 464 + lmHi + t * 32);
                    uint32_t ap[4] = { tmp[0], tmp[2], tmp[1], tmp[3] };
#pragma unroll
                    for (int nt = 0; nt < 8; nt++)
                        MMA16(okacc[mt][nt], ap,
                              bq[nt >> 1][(nt & 1) * 2], bq[nt >> 1][(nt & 1) * 2 + 1]);
                }
            }
        }
        __syncthreads();
    }

#pragma unroll
    for (int mt = 0; mt < 2; mt++) {
        if (mt == 0 || w < 6) {
            int t = w + mt * 8;
            int c0 = t * 16 + grp;
            if (c0 < NT) {
                __half* dst = act + ((long long)(b * NT + c0)) * ACTW + 768 + h * 64;
#pragma unroll
                for (int nt = 0; nt < 8; nt++)
                    *(__half2*)(dst + nt * 8 + 2 * tig) = __floats2half2_rn(okacc[mt][nt][0], okacc[mt][nt][1]);
            }
            if (c0 + 8 < NT) {
                __half* dst = act + ((long long)(b * NT + c0 + 8)) * ACTW + 768 + h * 64;
#pragma unroll
                for (int nt = 0; nt < 8; nt++)
                    *(__half2*)(dst + nt * 8 + 2 * tig) = __floats2half2_rn(okacc[mt][nt][2], okacc[mt][nt][3]);
            }
        }
    }
}

// ================= layernorm (fp32 in, half out) =================
__device__ __forceinline__ float block_sum256(float v, float* red) {
    int lane = threadIdx.x & 31, w = threadIdx.x >> 5;
#pragma unroll
    for (int o = 16; o > 0; o >>= 1) v += __shfl_xor_sync(0xffffffffu, v, o);
    if (lane == 0) red[w] = v;
    __syncthreads();
    float s = 0.f;
#pragma unroll
    for (int i = 0; i < 8; i++) s += red[i];
    __syncthreads();
    return s;
}

__global__ void lnorm_kernel(const float* __restrict__ x, __half* __restrict__ g,
                             const float* __restrict__ gamma_p,
                             const float* __restrict__ delta, int skipcls)
{
    __shared__ float red[8];
    int r = blockIdx.x;
    const float* xr;
    __half* gr;
    if (skipcls) {
        int b = r / NP, i = r - b * NP;
        xr = x + (long long)(b * NT + 1 + i) * D_;
        gr = g + (long long)r * D_;
    } else {
        xr = x + (long long)r * D_;
        gr = g + (long long)r * D_;
    }
    int t = threadIdx.x; // 256
    float v0 = xr[t], v1 = xr[t + 256], v2 = xr[t + 512];
    float mean = block_sum256(v0 + v1 + v2, red) * (1.f / 768.f);
    float c0 = v0 - mean, c1 = v1 - mean, c2 = v2 - mean;
    float var = block_sum256(c0*c0 + c1*c1 + c2*c2, red) * (1.f / 768.f);
    float rinv = rsqrtf(var + EPS_);
    float gm = gamma_p[0];
    gr[t]       = __float2half(gm * c0 * rinv + delta[t]);
    gr[t + 256] = __float2half(gm * c1 * rinv + delta[t + 256]);
    gr[t + 512] = __float2half(gm * c2 * rinv + delta[t + 512]);
}

// ================= weight prep =================
__global__ void build_wqk_kernel(const float* __restrict__ Wq, const float* __restrict__ Wk,
                                 __half* __restrict__ Wfwd, __half* __restrict__ Wback)
{
    int idx = blockIdx.x * 256 + threadIdx.x;
    if (idx >= 2 * D_ * D_) return;
    int which = idx >= D_ * D_;
    int r = idx - which * D_ * D_;
    int h = r / (D_ * Y_);
    int rem = r - h * (D_ * Y_);
    int d = rem / Y_;
    int y = rem - d * Y_;
    __half v = __float2half(which ? Wk[r] : Wq[r]);
    int hy = h * Y_ + y + which * D_;
    Wfwd[(long long)hy * D_ + d] = v;
    Wback[(long long)d * ACTW + hy] = v;
}

__global__ void build_xi_kernel(const float* __restrict__ Xi,
                                __half* __restrict__ Wfwd, __half* __restrict__ Wback)
{
    __shared__ __half t[32][33];
    int d0 = blockIdx.y * 32, m0 = blockIdx.x * 32;
    int tx = threadIdx.x & 31, ty = threadIdx.x >> 5;
#pragma unroll
    for (int i = 0; i < 32; i += 8) {
        __half v = __float2half(Xi[(long long)(d0 + ty + i) * M_ + m0 + tx]);
        Wback[(long long)(d0 + ty + i) * ACTW + 1536 + m0 + tx] = v;
        t[ty + i][tx] = v;
    }
    __syncthreads();
#pragma unroll
    for (int i = 0; i < 32; i += 8)
        Wfwd[(long long)(1536 + m0 + ty + i) * D_ + d0 + tx] = t[tx][ty + i];
}

__global__ void build_wt_kernel(const float* __restrict__ W, __half* __restrict__ WT)
{
    __shared__ __half t[32][33];
    int i0 = blockIdx.y * 32, j0 = blockIdx.x * 32;
    int tx = threadIdx.x & 31, ty = threadIdx.x >> 5;
#pragma unroll
    for (int i = 0; i < 32; i += 8)
        t[ty + i][tx] = __float2half(W[(long long)(i0 + ty + i) * D_ + j0 + tx]);
    __syncthreads();
#pragma unroll
    for (int i = 0; i < 32; i += 8)
        WT[(long long)(j0 + ty + i) * D_ + i0 + tx] = t[tx][ty + i];
}

// ================= misc =================
__global__ void patchify_kernel(const float* __restrict__ img, __half* __restrict__ out)
{
    int idx = blockIdx.x * 256 + threadIdx.x;
    if (idx >= B_ * NP * D_) return;
    int e = idx % D_;
    int rest = idx / D_;
    int p = rest % NP;
    int b = rest / NP;
    int c = e >> 8;
    int r = (e >> 4) & 15;
    int col = e & 15;
    int kh = p / 14, kw = p - kh * 14;
    out[idx] = __float2half(img[((long long)(b * 3 + c) * 224 + kh * 16 + r) * 224 + kw * 16 + col]);
}

__global__ void unpatchify_kernel(const float* __restrict__ dec, float* __restrict__ out)
{
    int idx = blockIdx.x * 256 + threadIdx.x;
    if (idx >= B_ * 3 * 224 * 224) return;
    int w = idx % 224;
    int rest = idx / 224;
    int h = rest % 224;
    rest /= 224;
    int c = rest % 3;
    int b = rest / 3;
    int kh = h >> 4, r = h & 15, kw = w >> 4, col = w & 15;
    out[idx] = dec[(long long)(b * NP + kh * 14 + kw) * D_ + c * 256 + r * 16 + col];
}

__global__ void build_x_kernel(const float* __restrict__ tok, const int* __restrict__ mask,
                               const float* __restrict__ cls, const float* __restrict__ mtok,
                               const float* __restrict__ pos, float* __restrict__ x)
{
    __shared__ int sm[NP];
    __shared__ unsigned char flag[NP];
    __shared__ int count_s;
    int b = blockIdx.x;
    int t = threadIdx.x; // 256
    if (t < NP) sm[t] = mask[b * NP + t];
    __syncthreads();
    if (t < NP) {
        int pref = 0;
        for (int j = 0; j < t; j++) pref += (sm[j] == 1);
        flag[t] = (sm[t] == 1 && pref < NMASK_) ? 1 : 0;
        if (t == NP - 1) count_s = pref + (sm[t] == 1);
    }
    __syncthreads();
    if (t == 0 && count_s < NMASK_) flag[0] = 1; // fill_value=0 padding hits token 0
    __syncthreads();
    for (int tk = 0; tk < NT; tk++) {
        const float* src;
        if (tk == 0) src = cls;
        else if (flag[tk - 1]) src = mtok;
        else src = tok + (long long)(b * NP + tk - 1) * D_;
        float* dst = x + (long long)(b * NT + tk) * D_;
        const float* pr = pos + (long long)tk * D_;
        for (int d = t; d < D_; d += 256) dst[d] = src[d] + pr[d];
    }
}

// ================= host wrappers =================
template<int EPI, int WM, bool GUARD>
static void launch_bt(const __half* A, const __half* B, void* C, void* C2,
                      const float* bias, int Mtiles, int Ntiles, int K,
                      int lda, int ldb, int ldc, int Mv, int Nv, float alpha)
{
    int smem = 3 * (WM * 32 + 128) * 40 * 2;
    cudaFuncSetAttribute(hbt_kernel<EPI, WM, GUARD>,
                         cudaFuncAttributeMaxDynamicSharedMemorySize, smem);
    dim3 g(Ntiles, Mtiles, 1);
    hbt_kernel<EPI, WM, GUARD><<<g, 128, smem>>>(A, B, C, C2, bias, K,
                                                 lda, ldb, ldc, Mv, Nv, alpha);
}

extern "C" void kernel_launch(void* const* d_in, const int* in_sizes, int n_in,
                              void* d_out, int out_size)
{
    const float* img   = (const float*)d_in[0];
    const int*   mask  = (const int*)  d_in[1];
    const float* enc_W = (const float*)d_in[2];
    const float* enc_b = (const float*)d_in[3];
    const float* dec_W = (const float*)d_in[4];
    const float* dec_b = (const float*)d_in[5];
    const float* cls   = (const float*)d_in[6];
    const float* mtok  = (const float*)d_in[7];
    const float* pos   = (const float*)d_in[8];
    const float* Wq    = (const float*)d_in[9];
    const float* Wk    = (const float*)d_in[10];
    const float* Xi    = (const float*)d_in[11];
    const float* gamma = (const float*)d_in[12];
    const float* delta = (const float*)d_in[13];
    float* out = (float*)d_out;

    __half *ppatH, *pgH, *pqkH, *pact, *pWfwd, *pWback, *pencTh, *pdecTh;
    float *ptok, *px, *pdec;
    cudaGetSymbolAddress((void**)&ppatH, d_patches);
    cudaGetSymbolAddress((void**)&ptok,  d_tok);
    cudaGetSymbolAddress((void**)&px,    d_x);
    cudaGetSymbolAddress((void**)&pgH,   d_g);
    cudaGetSymbolAddress((void**)&pqkH,  d_qk);
    cudaGetSymbolAddress((void**)&pact,  d_act);
    cudaGetSymbolAddress((void**)&pWfwd, d_Wfwd);
    cudaGetSymbolAddress((void**)&pWback, d_Wback);
    cudaGetSymbolAddress((void**)&pencTh, d_encTh);
    cudaGetSymbolAddress((void**)&pdecTh, d_decTh);
    cudaGetSymbolAddress((void**)&pdec,  d_dec);

    const int ROWS  = B_ * NT;   // 3152
    const int ROWSE = B_ * NP;   // 3136

    // weight prep
    build_wqk_kernel<<<(2 * D_ * D_ + 255) / 256, 256>>>(Wq, Wk, pWfwd, pWback);
    build_xi_kernel<<<dim3(M_ / 32, D_ / 32), 256>>>(Xi, pWfwd, pWback);
    build_wt_kernel<<<dim3(24, 24), 256>>>(enc_W, pencTh);
    build_wt_kernel<<<dim3(24, 24), 256>>>(dec_W, pdecTh);

    // encode
    patchify_kernel<<<(B_ * NP * D_ + 255) / 256, 256>>>(img, ppatH);
    launch_bt<EPI_BIAS, 4, true>(ppatH, pencTh, ptok, 0, enc_b,
        25, 6, D_, D_, D_, D_, ROWSE, D_, 0.f);
    build_x_kernel<<<B_, 256>>>(ptok, mask, cls, mtok, pos, px);

    int attn_smem = (2 * 256 * 72 + 128 * 232) * 2;   // 133120
    cudaFuncSetAttribute(attn_kernel,
                         cudaFuncAttributeMaxDynamicSharedMemorySize, attn_smem);

    for (int s = 0; s < NSTEPS_; s++) {
        lnorm_kernel<<<ROWS, 256>>>(px, pgH, gamma, delta, 0);
        // fused fwd: [q|k | Z] = g @ [WT ; XiT]  (q|k -> d_qk, relu(Z) -> d_act)
        launch_bt<EPI_QKZ, 4, false>(pgH, pWfwd, pqkH, pact, 0,
            25, 36, D_, D_, D_, 0, 0, 0, 0.f);
        // fused attention: act[.,0..1535] <- [P@k | P^T@q]
        attn_kernel<<<B_ * HEADS_, 256, attn_smem>>>(pqkH, pact);
        // fused bwd: x += alpha * [oq|ok|Z] @ [W2 ; XiR]
        launch_bt<EPI_AXPY, 2, false>(pact, pWback, px, 0, 0,
            50, 6, ACTW, ACTW, ACTW, D_, 0, 0, ALPHA_);
    }

    // decode
    lnorm_kernel<<<ROWSE, 256>>>(px, pgH, gamma, delta, 1);
    launch_bt<EPI_BIAS, 4, true>(pgH, pdecTh, pdec, 0, dec_b,
        25, 6, D_, D_, D_, D_, ROWSE, D_, 0.f);
    unpatchify_kernel<<<(B_ * 3 * 224 * 224 + 255) / 256, 256>>>(pdec, out);
}